// round 1
// baseline (speedup 1.0000x reference)
#include <cuda_runtime.h>
#include <cstdint>

#define Bsz 16
#define Ntok 4096
#define Cch 384
#define HRES 64
#define NH 12
#define DH 32
#define TWOC 768

static const size_t BNC = (size_t)Bsz * Ntok * Cch;   // 25,165,824

// Scratch (device globals: allocation-free rule)
__device__ float  g_q [Bsz * Ntok * Cch];   // unroped q (for z)
__device__ float  g_qr[Bsz * Ntok * Cch];   // roped q
__device__ float  g_kr[Bsz * Ntok * Cch];   // roped k
__device__ float  g_ksum[Bsz * Cch];        // sum_n k (unroped)
__device__ float  g_kv  [Bsz * NH * DH * DH];
__device__ float2 g_rope[Ntok * (Cch / 2)]; // cos/sin per (token, pair)

// ---------------------------------------------------------------------------
// RoPE table: angle(p<96)=hh*theta[p], angle(p>=96)=ww*theta[p-96]
// ---------------------------------------------------------------------------
__global__ void rope_table_kernel() {
    int n = blockIdx.x;          // 0..4095
    int p = threadIdx.x;         // 0..191
    int hh = n >> 6, ww = n & 63;
    int j = (p < 96) ? p : (p - 96);
    float theta = __expf(-((float)j * (1.0f / 96.0f)) * 9.210340371976184f); // 10000^(-j/96)
    float pos = (p < 96) ? (float)hh : (float)ww;
    float s, c;
    sincosf(pos * theta, &s, &c);
    g_rope[(size_t)n * 192 + p] = make_float2(c, s);
}

__global__ void zero_ksum_kernel() {
    int i = blockIdx.x * blockDim.x + threadIdx.x;
    if (i < Bsz * Cch) g_ksum[i] = 0.f;
}

// ---------------------------------------------------------------------------
// GEMM qk = x @ W^T + b, fused elu+1, RoPE, k-sum
// BM=128 BN=64 BK=16, 256 threads, 8x4 per thread
// grid: (512, 12); y<6 -> q half, y>=6 -> k half
// ---------------------------------------------------------------------------
#define BM 128
#define BN 64
#define BK 16

__global__ __launch_bounds__(256) void gemm_rope_kernel(
    const float* __restrict__ x, const float* __restrict__ w,
    const float* __restrict__ bias)
{
    __shared__ float As[BK][BM + 2];
    __shared__ float Ws[BK][BN + 2];
    __shared__ float red[BN];

    int tid = threadIdx.x;
    int mBase = blockIdx.x * BM;
    int jBase = blockIdx.y * BN;
    int ty = tid >> 4, tx = tid & 15;

    float acc[8][4];
#pragma unroll
    for (int r = 0; r < 8; r++)
#pragma unroll
        for (int c = 0; c < 4; c++) acc[r][c] = 0.f;

    const float* xblk = x + (size_t)mBase * Cch;
    const float* wblk = w + (size_t)jBase * Cch;

    for (int k0 = 0; k0 < Cch; k0 += BK) {
#pragma unroll
        for (int i = 0; i < 2; i++) {
            int idx = tid * 2 + i;            // 0..511
            int m = idx >> 2, k4 = idx & 3;
            float4 v = *(const float4*)(xblk + (size_t)m * Cch + k0 + k4 * 4);
            As[k4 * 4 + 0][m] = v.x; As[k4 * 4 + 1][m] = v.y;
            As[k4 * 4 + 2][m] = v.z; As[k4 * 4 + 3][m] = v.w;
        }
        {
            int j = tid >> 2, k4 = tid & 3;
            float4 v = *(const float4*)(wblk + (size_t)j * Cch + k0 + k4 * 4);
            Ws[k4 * 4 + 0][j] = v.x; Ws[k4 * 4 + 1][j] = v.y;
            Ws[k4 * 4 + 2][j] = v.z; Ws[k4 * 4 + 3][j] = v.w;
        }
        __syncthreads();
#pragma unroll
        for (int k = 0; k < BK; k++) {
            float a[8], bf[4];
#pragma unroll
            for (int r = 0; r < 8; r++) a[r] = As[k][ty * 8 + r];
#pragma unroll
            for (int c = 0; c < 4; c++) bf[c] = Ws[k][tx + 16 * c];
#pragma unroll
            for (int r = 0; r < 8; r++)
#pragma unroll
                for (int c = 0; c < 4; c++) acc[r][c] += a[r] * bf[c];
        }
        __syncthreads();
    }

    // ---- fused epilogue ----
    bool isK = (jBase >= Cch);
    int b = mBase >> 12;
    float ksum_part[4] = {0.f, 0.f, 0.f, 0.f};
    bool even = ((tx & 1) == 0);

#pragma unroll
    for (int c = 0; c < 4; c++) {
        int j = jBase + tx + 16 * c;
        int jm = isK ? (j - Cch) : j;
        int p = jm >> 1;
        float bj = bias[j];
#pragma unroll
        for (int r = 0; r < 8; r++) {
            int m = mBase + ty * 8 + r;
            int n = m & (Ntok - 1);
            float v = acc[r][c] + bj;
            v = (v > 0.f) ? (v + 1.f) : __expf(v);          // elu(v)+1
            float pv = __shfl_xor_sync(0xffffffffu, v, 1);  // pair partner
            float2 cs = g_rope[(size_t)n * 192 + p];
            float rot = even ? (cs.x * v - cs.y * pv) : (cs.x * v + cs.y * pv);
            size_t off = (size_t)m * Cch + jm;
            if (!isK) {
                g_q[off]  = v;
                g_qr[off] = rot;
            } else {
                g_kr[off] = rot;
                ksum_part[c] += v;
            }
        }
    }

    if (isK) {
        if (tid < BN) red[tid] = 0.f;
        __syncthreads();
#pragma unroll
        for (int c = 0; c < 4; c++)
            atomicAdd(&red[tx + 16 * c], ksum_part[c]);
        __syncthreads();
        if (tid < BN)
            atomicAdd(&g_ksum[b * Cch + (jBase - Cch) + tid], red[tid]);
    }
}

// ---------------------------------------------------------------------------
// kv[b][h] = (1/N) sum_n outer(k_rope[b,n,h,:], x[b,n,h,:])   (32x32, K=4096)
// grid (16,12), 256 threads, 2x2 microtile
// ---------------------------------------------------------------------------
__global__ __launch_bounds__(256) void kv_kernel(const float* __restrict__ x)
{
    int b = blockIdx.x, h = blockIdx.y;
    int tid = threadIdx.x;
    __shared__ float ks[64][32];
    __shared__ float vs[64][32];

    int d0 = (tid >> 4) * 2;   // 0..30
    int e0 = (tid & 15) * 2;   // 0..30
    float a00 = 0.f, a01 = 0.f, a10 = 0.f, a11 = 0.f;

    const float* kr = g_kr + ((size_t)b * Ntok) * Cch + h * DH;
    const float* vv = x    + ((size_t)b * Ntok) * Cch + h * DH;

    for (int n0 = 0; n0 < Ntok; n0 += 64) {
        for (int i = tid; i < 64 * 32; i += 256) {
            int n = i >> 5, e = i & 31;
            ks[n][e] = kr[(size_t)(n0 + n) * Cch + e];
            vs[n][e] = vv[(size_t)(n0 + n) * Cch + e];
        }
        __syncthreads();
#pragma unroll 8
        for (int n = 0; n < 64; n++) {
            float k0v = ks[n][d0], k1v = ks[n][d0 + 1];
            float v0 = vs[n][e0],  v1 = vs[n][e0 + 1];
            a00 += k0v * v0; a01 += k0v * v1;
            a10 += k1v * v0; a11 += k1v * v1;
        }
        __syncthreads();
    }
    const float inv = 1.0f / (float)Ntok;
    size_t base = ((size_t)(b * NH + h) * DH);
    g_kv[(base + d0)     * DH + e0]     = a00 * inv;
    g_kv[(base + d0)     * DH + e0 + 1] = a01 * inv;
    g_kv[(base + d0 + 1) * DH + e0]     = a10 * inv;
    g_kv[(base + d0 + 1) * DH + e0 + 1] = a11 * inv;
}

// ---------------------------------------------------------------------------
// Finalize: out = (q_rope @ kv[b,h]) * z + lepe(conv3x3 dw) + bias
// grid (64 rows, 16 batch), 384 threads (thread = output channel)
// ---------------------------------------------------------------------------
__global__ __launch_bounds__(384) void finalize_kernel(
    const float* __restrict__ x, const float* __restrict__ lepe_w,
    const float* __restrict__ lepe_b, float* __restrict__ out)
{
    extern __shared__ float sm[];
    float* kv_s    = sm;                 // 12*32*32 = 12288
    float* kmean_s = kv_s + NH * DH * DH;
    float* qr_s    = kmean_s + Cch;      // 384
    float* z_s     = qr_s + Cch;         // 12

    int hh = blockIdx.x, b = blockIdx.y;
    int t = threadIdx.x;
    int h = t >> 5, lane = t & 31;

    // stage kv for this batch
    {
        const float* src = g_kv + (size_t)b * NH * DH * DH;
        for (int i = t; i < NH * DH * DH; i += 384) kv_s[i] = src[i];
        kmean_s[t] = g_ksum[b * Cch + t] * (1.0f / (float)Ntok);
    }
    // per-thread conv weights (channel fixed)
    float wl[9];
#pragma unroll
    for (int i = 0; i < 9; i++) wl[i] = lepe_w[t * 9 + i];
    float lb = lepe_b[t];
    __syncthreads();

    const float* kvh = &kv_s[h * DH * DH];

    for (int ww = 0; ww < HRES; ww++) {
        int n = hh * HRES + ww;
        size_t g = ((size_t)b * Ntok + n) * Cch;

        float qv = g_q[g + t];
        qr_s[t] = g_qr[g + t];
        float prod = qv * kmean_s[t];
#pragma unroll
        for (int o = 16; o > 0; o >>= 1)
            prod += __shfl_xor_sync(0xffffffffu, prod, o);
        if (lane == 0) z_s[h] = 1.0f / (prod + 1e-6f);
        __syncthreads();

        float accv = 0.f;
#pragma unroll
        for (int d = 0; d < DH; d++)
            accv += qr_s[h * DH + d] * kvh[d * DH + lane];
        float res = accv * z_s[h];

        // depthwise 3x3 conv, SAME padding
        float lp = lb;
#pragma unroll
        for (int dy = -1; dy <= 1; dy++) {
            int yy = hh + dy;
            if (yy < 0 || yy >= HRES) continue;
#pragma unroll
            for (int dx = -1; dx <= 1; dx++) {
                int xx = ww + dx;
                if (xx < 0 || xx >= HRES) continue;
                lp += x[((size_t)b * Ntok + yy * HRES + xx) * Cch + t]
                      * wl[(dy + 1) * 3 + (dx + 1)];
            }
        }
        out[g + t] = res + lp;
        __syncthreads();
    }
}

// ---------------------------------------------------------------------------
extern "C" void kernel_launch(void* const* d_in, const int* in_sizes, int n_in,
                              void* d_out, int out_size)
{
    const float* x      = (const float*)d_in[0];
    const float* qk_w   = (const float*)d_in[1];
    const float* qk_b   = (const float*)d_in[2];
    const float* lepe_w = (const float*)d_in[3];
    const float* lepe_b = (const float*)d_in[4];
    float* out = (float*)d_out;

    static bool attr_set = false;
    size_t fin_smem = (size_t)(NH * DH * DH + Cch + Cch + 16) * sizeof(float);
    if (!attr_set) {
        cudaFuncSetAttribute(finalize_kernel,
                             cudaFuncAttributeMaxDynamicSharedMemorySize,
                             (int)fin_smem);
        attr_set = true;
    }

    rope_table_kernel<<<Ntok, 192>>>();
    zero_ksum_kernel<<<(Bsz * Cch + 255) / 256, 256>>>();
    gemm_rope_kernel<<<dim3((Bsz * Ntok) / BM, TWOC / BN), 256>>>(x, qk_w, qk_b);
    kv_kernel<<<dim3(Bsz, NH), 256>>>(x);
    finalize_kernel<<<dim3(HRES, Bsz), 384, fin_smem>>>(x, lepe_w, lepe_b, out);
}

// round 2
// speedup vs baseline: 2.0900x; 2.0900x over previous
#include <cuda_runtime.h>
#include <cstdint>

#define Bsz 16
#define Ntok 4096
#define Cch 384
#define HRES 64
#define NH 12
#define DH 32
#define TWOC 768

// Scratch (device globals: allocation-free rule)
__device__ float  g_q [Bsz * Ntok * Cch];   // unroped q (for z)
__device__ float  g_qr[Bsz * Ntok * Cch];   // roped q
__device__ float  g_kr[Bsz * Ntok * Cch];   // roped k
__device__ float  g_ksum[Bsz * Cch];        // sum_n k (unroped)
__device__ float  g_kv  [Bsz * NH * DH * DH];
__device__ float2 g_rope[Ntok * (Cch / 2)]; // cos/sin per (token, pair)

// ---------------------------------------------------------------------------
__global__ void rope_table_kernel() {
    int n = blockIdx.x;          // 0..4095
    int p = threadIdx.x;         // 0..191
    int hh = n >> 6, ww = n & 63;
    int j = (p < 96) ? p : (p - 96);
    float theta = __expf(-((float)j * (1.0f / 96.0f)) * 9.210340371976184f); // 10000^(-j/96)
    float pos = (p < 96) ? (float)hh : (float)ww;
    float s, c;
    sincosf(pos * theta, &s, &c);
    g_rope[(size_t)n * 192 + p] = make_float2(c, s);
}

__global__ void zero_scratch_kernel() {
    int i = blockIdx.x * blockDim.x + threadIdx.x;
    if (i < Bsz * Cch) g_ksum[i] = 0.f;
    if (i < Bsz * NH * DH * DH) g_kv[i] = 0.f;
}

// ---------------------------------------------------------------------------
// tf32 helpers
// ---------------------------------------------------------------------------
__device__ __forceinline__ uint32_t f2tf(float f) {
    uint32_t r;
    asm("cvt.rna.tf32.f32 %0, %1;" : "=r"(r) : "f"(f));
    return r;
}

__device__ __forceinline__ void mma8(float4& d, const uint32_t* a, const uint32_t* b) {
    asm volatile(
        "mma.sync.aligned.m16n8k8.row.col.f32.tf32.tf32.f32 "
        "{%0,%1,%2,%3},{%4,%5,%6,%7},{%8,%9},{%0,%1,%2,%3};\n"
        : "+f"(d.x), "+f"(d.y), "+f"(d.z), "+f"(d.w)
        : "r"(a[0]), "r"(a[1]), "r"(a[2]), "r"(a[3]), "r"(b[0]), "r"(b[1]));
}

// ---------------------------------------------------------------------------
// GEMM qk = x @ W^T + b via tf32 MMA, fused elu+1, RoPE, k-sum
// BM=128 BN=64 BK=32, 256 threads (8 warps, 4x2), warp tile 32x32
// grid (12 j-blocks [fast], 512 m-blocks) -> A tiles shared across j via L2
// ---------------------------------------------------------------------------
#define BM 128
#define BN 64
#define BK 32
#define LDA 36
#define LDB 36

__global__ __launch_bounds__(256) void gemm_rope_tc(
    const float* __restrict__ x, const float* __restrict__ w,
    const float* __restrict__ bias)
{
    __shared__ uint32_t As[BM * LDA];   // tf32 bits
    __shared__ uint32_t Ws[BN * LDB];

    int tid  = threadIdx.x;
    int warp = tid >> 5, lane = tid & 31;
    int wm = warp >> 1, wn = warp & 1;
    int g  = lane >> 2, l4 = lane & 3;

    int jBase = blockIdx.x * BN;
    int mBase = blockIdx.y * BM;

    const float* xblk = x + (size_t)mBase * Cch;
    const float* wblk = w + (size_t)jBase * Cch;

    float4 c[2][4];
#pragma unroll
    for (int i = 0; i < 2; i++)
#pragma unroll
        for (int f = 0; f < 4; f++) c[i][f] = make_float4(0.f, 0.f, 0.f, 0.f);

    for (int k0 = 0; k0 < Cch; k0 += BK) {
        // A: 128 rows x 32 cols = 1024 float4; 4 per thread
#pragma unroll
        for (int i = 0; i < 4; i++) {
            int idx = tid + i * 256;
            int m = idx >> 3, kq = idx & 7;
            float4 v = *(const float4*)(xblk + (size_t)m * Cch + k0 + kq * 4);
            uint4 u = make_uint4(f2tf(v.x), f2tf(v.y), f2tf(v.z), f2tf(v.w));
            *(uint4*)&As[m * LDA + kq * 4] = u;
        }
        // W: 64 rows x 32 cols = 512 float4; 2 per thread
#pragma unroll
        for (int i = 0; i < 2; i++) {
            int idx = tid + i * 256;
            int j = idx >> 3, kq = idx & 7;
            float4 v = *(const float4*)(wblk + (size_t)j * Cch + k0 + kq * 4);
            uint4 u = make_uint4(f2tf(v.x), f2tf(v.y), f2tf(v.z), f2tf(v.w));
            *(uint4*)&Ws[j * LDB + kq * 4] = u;
        }
        __syncthreads();

#pragma unroll
        for (int ks = 0; ks < BK; ks += 8) {
            uint32_t a[2][4], b[4][2];
#pragma unroll
            for (int i = 0; i < 2; i++) {
                int m = wm * 32 + i * 16;
                a[i][0] = As[(m + g) * LDA + ks + l4];
                a[i][1] = As[(m + g + 8) * LDA + ks + l4];
                a[i][2] = As[(m + g) * LDA + ks + l4 + 4];
                a[i][3] = As[(m + g + 8) * LDA + ks + l4 + 4];
            }
#pragma unroll
            for (int f = 0; f < 4; f++) {
                int j = wn * 32 + f * 8;
                b[f][0] = Ws[(j + g) * LDB + ks + l4];
                b[f][1] = Ws[(j + g) * LDB + ks + l4 + 4];
            }
#pragma unroll
            for (int i = 0; i < 2; i++)
#pragma unroll
                for (int f = 0; f < 4; f++) mma8(c[i][f], a[i], b[f]);
        }
        __syncthreads();
    }

    // ---- fused epilogue ----
    bool isK = (jBase >= Cch);
    int bb = mBase >> 12;
    float ksum_loc[4][2];
#pragma unroll
    for (int f = 0; f < 4; f++) { ksum_loc[f][0] = 0.f; ksum_loc[f][1] = 0.f; }

#pragma unroll
    for (int i = 0; i < 2; i++) {
        int mrow0 = mBase + wm * 32 + i * 16 + g;
#pragma unroll
        for (int f = 0; f < 4; f++) {
            int j0 = jBase + wn * 32 + f * 8 + 2 * l4;
            int jm = isK ? (j0 - Cch) : j0;
            float b0 = bias[j0], b1 = bias[j0 + 1];
#pragma unroll
            for (int rr = 0; rr < 2; rr++) {
                int m = mrow0 + rr * 8;
                float re = (rr == 0 ? c[i][f].x : c[i][f].z) + b0;
                float im = (rr == 0 ? c[i][f].y : c[i][f].w) + b1;
                re = (re > 0.f) ? (re + 1.f) : __expf(re);
                im = (im > 0.f) ? (im + 1.f) : __expf(im);
                int n = m & (Ntok - 1);
                float2 cs = g_rope[(size_t)n * 192 + (jm >> 1)];
                float rre = cs.x * re - cs.y * im;
                float rim = cs.y * re + cs.x * im;
                size_t off = (size_t)m * Cch + jm;
                if (!isK) {
                    *(float2*)&g_q [off] = make_float2(re, im);
                    *(float2*)&g_qr[off] = make_float2(rre, rim);
                } else {
                    *(float2*)&g_kr[off] = make_float2(rre, rim);
                    ksum_loc[f][0] += re;
                    ksum_loc[f][1] += im;
                }
            }
        }
    }

    if (isK) {
#pragma unroll
        for (int f = 0; f < 4; f++) {
#pragma unroll
            for (int e = 0; e < 2; e++) {
                float v = ksum_loc[f][e];
                v += __shfl_xor_sync(0xffffffffu, v, 4);
                v += __shfl_xor_sync(0xffffffffu, v, 8);
                v += __shfl_xor_sync(0xffffffffu, v, 16);
                if (g == 0) {
                    int jm = (jBase - Cch) + wn * 32 + f * 8 + 2 * l4 + e;
                    atomicAdd(&g_ksum[bb * Cch + jm], v);
                }
            }
        }
    }
}

// ---------------------------------------------------------------------------
// kv[b][h] += (1/N) sum_{n in chunk} outer(k_rope, v);  8-way split over N
// grid (16, 12, 8), 256 threads, 2x2 microtile
// ---------------------------------------------------------------------------
__global__ __launch_bounds__(256) void kv_kernel(const float* __restrict__ x)
{
    int b = blockIdx.x, h = blockIdx.y, s = blockIdx.z;
    int tid = threadIdx.x;
    __shared__ float ks[64][32];
    __shared__ float vs[64][32];

    int d0 = (tid >> 4) * 2;
    int e0 = (tid & 15) * 2;
    float a00 = 0.f, a01 = 0.f, a10 = 0.f, a11 = 0.f;

    int nBase = s * 512;
    const float* kr = g_kr + ((size_t)b * Ntok + nBase) * Cch + h * DH;
    const float* vv = x    + ((size_t)b * Ntok + nBase) * Cch + h * DH;

    for (int n0 = 0; n0 < 512; n0 += 64) {
        for (int i = tid; i < 64 * 32; i += 256) {
            int n = i >> 5, e = i & 31;
            ks[n][e] = kr[(size_t)(n0 + n) * Cch + e];
            vs[n][e] = vv[(size_t)(n0 + n) * Cch + e];
        }
        __syncthreads();
#pragma unroll 8
        for (int n = 0; n < 64; n++) {
            float k0v = ks[n][d0], k1v = ks[n][d0 + 1];
            float v0 = vs[n][e0],  v1 = vs[n][e0 + 1];
            a00 += k0v * v0; a01 += k0v * v1;
            a10 += k1v * v0; a11 += k1v * v1;
        }
        __syncthreads();
    }
    const float inv = 1.0f / (float)Ntok;
    size_t base = (size_t)(b * NH + h) * DH;
    atomicAdd(&g_kv[(base + d0)     * DH + e0],     a00 * inv);
    atomicAdd(&g_kv[(base + d0)     * DH + e0 + 1], a01 * inv);
    atomicAdd(&g_kv[(base + d0 + 1) * DH + e0],     a10 * inv);
    atomicAdd(&g_kv[(base + d0 + 1) * DH + e0 + 1], a11 * inv);
}

// ---------------------------------------------------------------------------
// Finalize: out = (q_rope @ kv[b,h]) * z + dw-conv3x3(x) + bias
// head == warp: all reductions warp-local, no __syncthreads in loop.
// kv column cached in 32 registers; rolling conv window in registers.
// grid (64 rows, 16 batch), 384 threads (thread = channel)
// ---------------------------------------------------------------------------
__global__ __launch_bounds__(384) void finalize_kernel(
    const float* __restrict__ x, const float* __restrict__ lepe_w,
    const float* __restrict__ lepe_b, float* __restrict__ out)
{
    int hh = blockIdx.x, b = blockIdx.y;
    int t = threadIdx.x;
    int h = t >> 5, lane = t & 31;

    float kmean = g_ksum[b * Cch + t] * (1.0f / (float)Ntok);

    float wl[9];
#pragma unroll
    for (int i = 0; i < 9; i++) wl[i] = lepe_w[t * 9 + i];
    float lb = lepe_b[t];

    // kv column for this (head, lane): kv[b,h][d][lane], d = 0..31
    float kvcol[DH];
    {
        const float* kvh = g_kv + (size_t)(b * NH + h) * DH * DH;
#pragma unroll
        for (int d = 0; d < DH; d++) kvcol[d] = kvh[d * DH + lane];
    }

    // rolling conv window: rows hh-1..hh+1, columns ww-1, ww, ww+1
    const size_t rowStride = (size_t)HRES * Cch;
    const float* xb = x + (size_t)b * Ntok * Cch + t;
    bool rok[3];
    const float* xr[3];
#pragma unroll
    for (int r = 0; r < 3; r++) {
        int yy = hh - 1 + r;
        rok[r] = (yy >= 0 && yy < HRES);
        xr[r] = xb + (size_t)(rok[r] ? yy : 0) * rowStride;
    }
    float cprev[3], ccur[3], cnext[3];
#pragma unroll
    for (int r = 0; r < 3; r++) {
        cprev[r] = 0.f;
        ccur[r]  = rok[r] ? xr[r][0]        : 0.f;
        cnext[r] = rok[r] ? xr[r][(size_t)Cch] : 0.f;
    }

    const float* qrow  = g_q  + ((size_t)b * Ntok + (size_t)hh * HRES) * Cch + t;
    const float* qrrow = g_qr + ((size_t)b * Ntok + (size_t)hh * HRES) * Cch + t;
    float* orow = out + ((size_t)b * Ntok + (size_t)hh * HRES) * Cch + t;

    for (int ww = 0; ww < HRES; ww++) {
        size_t g = (size_t)ww * Cch;
        float qv  = qrow[g];
        float qrv = qrrow[g];

        // z = 1 / (q . k_mean + eps)  (warp-local reduce)
        float prod = qv * kmean;
#pragma unroll
        for (int o = 16; o > 0; o >>= 1)
            prod += __shfl_xor_sync(0xffffffffu, prod, o);
        float z = 1.0f / (prod + 1e-6f);

        // q_rope @ kv : broadcast each q_rope[d] within the warp
        float accv = 0.f;
#pragma unroll
        for (int d = 0; d < DH; d++)
            accv += __shfl_sync(0xffffffffu, qrv, d) * kvcol[d];
        float res = accv * z;

        // depthwise 3x3
        float lp = lb;
#pragma unroll
        for (int r = 0; r < 3; r++)
            lp += cprev[r] * wl[r * 3 + 0] + ccur[r] * wl[r * 3 + 1]
                + cnext[r] * wl[r * 3 + 2];

        orow[g] = res + lp;

        // shift window
#pragma unroll
        for (int r = 0; r < 3; r++) { cprev[r] = ccur[r]; ccur[r] = cnext[r]; }
        int xx = ww + 2;
        bool cok = (xx < HRES);
#pragma unroll
        for (int r = 0; r < 3; r++)
            cnext[r] = (rok[r] && cok) ? xr[r][(size_t)xx * Cch] : 0.f;
    }
}

// ---------------------------------------------------------------------------
extern "C" void kernel_launch(void* const* d_in, const int* in_sizes, int n_in,
                              void* d_out, int out_size)
{
    const float* x      = (const float*)d_in[0];
    const float* qk_w   = (const float*)d_in[1];
    const float* qk_b   = (const float*)d_in[2];
    const float* lepe_w = (const float*)d_in[3];
    const float* lepe_b = (const float*)d_in[4];
    float* out = (float*)d_out;

    rope_table_kernel<<<Ntok, 192>>>();
    int zn = Bsz * NH * DH * DH;  // 196608 >= Bsz*Cch
    zero_scratch_kernel<<<(zn + 255) / 256, 256>>>();
    gemm_rope_tc<<<dim3(TWOC / BN, (Bsz * Ntok) / BM), 256>>>(x, qk_w, qk_b);
    kv_kernel<<<dim3(Bsz, NH, 8), 256>>>(x);
    finalize_kernel<<<dim3(HRES, Bsz), 384>>>(x, lepe_w, lepe_b, out);
}

// round 3
// speedup vs baseline: 2.2585x; 1.0806x over previous
#include <cuda_runtime.h>
#include <cstdint>

#define Bsz 16
#define Ntok 4096
#define Cch 384
#define HRES 64
#define NH 12
#define DH 32
#define TWOC 768

// Scratch (device globals: allocation-free rule)
__device__ float  g_qr[Bsz * Ntok * Cch];   // roped q
__device__ float  g_kr[Bsz * Ntok * Cch];   // roped k
__device__ float  g_ksum[Bsz * Cch];        // sum_n k (unroped)
__device__ float  g_kv  [Bsz * NH * DH * DH];
__device__ float2 g_rope[Ntok * (Cch / 2)]; // cos/sin per (token, pair)

// ---------------------------------------------------------------------------
__global__ void rope_table_kernel() {
    int n = blockIdx.x;          // 0..4095
    int p = threadIdx.x;         // 0..191
    int hh = n >> 6, ww = n & 63;
    int j = (p < 96) ? p : (p - 96);
    float theta = __expf(-((float)j * (1.0f / 96.0f)) * 9.210340371976184f); // 10000^(-j/96)
    float pos = (p < 96) ? (float)hh : (float)ww;
    float s, c;
    sincosf(pos * theta, &s, &c);
    g_rope[(size_t)n * 192 + p] = make_float2(c, s);
}

__global__ void zero_scratch_kernel() {
    int i = blockIdx.x * blockDim.x + threadIdx.x;
    if (i < Bsz * Cch) g_ksum[i] = 0.f;
    if (i < Bsz * NH * DH * DH) g_kv[i] = 0.f;
}

// ---------------------------------------------------------------------------
// tf32 helpers
// ---------------------------------------------------------------------------
__device__ __forceinline__ uint32_t f2tf(float f) {
    uint32_t r;
    asm("cvt.rna.tf32.f32 %0, %1;" : "=r"(r) : "f"(f));
    return r;
}

__device__ __forceinline__ uint4 cvt4(float4 v) {
    return make_uint4(f2tf(v.x), f2tf(v.y), f2tf(v.z), f2tf(v.w));
}

__device__ __forceinline__ void mma8(float4& d, const uint32_t* a, const uint32_t* b) {
    asm volatile(
        "mma.sync.aligned.m16n8k8.row.col.f32.tf32.tf32.f32 "
        "{%0,%1,%2,%3},{%4,%5,%6,%7},{%8,%9},{%0,%1,%2,%3};\n"
        : "+f"(d.x), "+f"(d.y), "+f"(d.z), "+f"(d.w)
        : "r"(a[0]), "r"(a[1]), "r"(a[2]), "r"(a[3]), "r"(b[0]), "r"(b[1]));
}

// ---------------------------------------------------------------------------
// GEMM qk = x @ W^T + b via tf32 MMA, fused elu+1, RoPE, k-sum
// BM=128 BN=64 BK=32, 256 threads (8 warps, 4x2), warp tile 32x32
// register double-buffer: LDG next tile overlaps MMA of current tile
// grid (12 j-blocks [fast], 512 m-blocks) -> A tiles shared across j via L2
// ---------------------------------------------------------------------------
#define BM 128
#define BN 64
#define BK 32
#define LDA 36
#define LDB 36

__global__ __launch_bounds__(256) void gemm_rope_tc(
    const float* __restrict__ x, const float* __restrict__ w,
    const float* __restrict__ bias)
{
    __shared__ uint32_t As[BM * LDA];   // tf32 bits
    __shared__ uint32_t Ws[BN * LDB];

    int tid  = threadIdx.x;
    int warp = tid >> 5, lane = tid & 31;
    int wm = warp >> 1, wn = warp & 1;
    int g  = lane >> 2, l4 = lane & 3;

    int jBase = blockIdx.x * BN;
    int mBase = blockIdx.y * BM;

    const float* xblk = x + (size_t)mBase * Cch;
    const float* wblk = w + (size_t)jBase * Cch;

    // per-thread loader coordinates (constant)
    int am[4], ak[4], wj[2], wk[2];
#pragma unroll
    for (int i = 0; i < 4; i++) { int idx = tid + i * 256; am[i] = idx >> 3; ak[i] = (idx & 7) * 4; }
#pragma unroll
    for (int i = 0; i < 2; i++) { int idx = tid + i * 256; wj[i] = idx >> 3; wk[i] = (idx & 7) * 4; }

    float4 c[2][4];
#pragma unroll
    for (int i = 0; i < 2; i++)
#pragma unroll
        for (int f = 0; f < 4; f++) c[i][f] = make_float4(0.f, 0.f, 0.f, 0.f);

    float4 ra[4], rw[2];
#pragma unroll
    for (int i = 0; i < 4; i++) ra[i] = *(const float4*)(xblk + (size_t)am[i] * Cch + ak[i]);
#pragma unroll
    for (int i = 0; i < 2; i++) rw[i] = *(const float4*)(wblk + (size_t)wj[i] * Cch + wk[i]);

    for (int k0 = 0; k0 < Cch; k0 += BK) {
        __syncthreads();   // previous compute done before overwrite
#pragma unroll
        for (int i = 0; i < 4; i++) *(uint4*)&As[am[i] * LDA + ak[i]] = cvt4(ra[i]);
#pragma unroll
        for (int i = 0; i < 2; i++) *(uint4*)&Ws[wj[i] * LDB + wk[i]] = cvt4(rw[i]);
        __syncthreads();

        int kn = k0 + BK;
        if (kn < Cch) {
#pragma unroll
            for (int i = 0; i < 4; i++) ra[i] = *(const float4*)(xblk + (size_t)am[i] * Cch + kn + ak[i]);
#pragma unroll
            for (int i = 0; i < 2; i++) rw[i] = *(const float4*)(wblk + (size_t)wj[i] * Cch + kn + wk[i]);
        }

#pragma unroll
        for (int ks = 0; ks < BK; ks += 8) {
            uint32_t a[2][4], b[4][2];
#pragma unroll
            for (int i = 0; i < 2; i++) {
                int m = wm * 32 + i * 16;
                a[i][0] = As[(m + g) * LDA + ks + l4];
                a[i][1] = As[(m + g + 8) * LDA + ks + l4];
                a[i][2] = As[(m + g) * LDA + ks + l4 + 4];
                a[i][3] = As[(m + g + 8) * LDA + ks + l4 + 4];
            }
#pragma unroll
            for (int f = 0; f < 4; f++) {
                int j = wn * 32 + f * 8;
                b[f][0] = Ws[(j + g) * LDB + ks + l4];
                b[f][1] = Ws[(j + g) * LDB + ks + l4 + 4];
            }
#pragma unroll
            for (int i = 0; i < 2; i++)
#pragma unroll
                for (int f = 0; f < 4; f++) mma8(c[i][f], a[i], b[f]);
        }
    }

    // ---- fused epilogue ----
    bool isK = (jBase >= Cch);
    int bb = mBase >> 12;
    float ksum_loc[4][2];
#pragma unroll
    for (int f = 0; f < 4; f++) { ksum_loc[f][0] = 0.f; ksum_loc[f][1] = 0.f; }

#pragma unroll
    for (int i = 0; i < 2; i++) {
        int mrow0 = mBase + wm * 32 + i * 16 + g;
#pragma unroll
        for (int f = 0; f < 4; f++) {
            int j0 = jBase + wn * 32 + f * 8 + 2 * l4;
            int jm = isK ? (j0 - Cch) : j0;
            float b0 = bias[j0], b1 = bias[j0 + 1];
#pragma unroll
            for (int rr = 0; rr < 2; rr++) {
                int m = mrow0 + rr * 8;
                float re = (rr == 0 ? c[i][f].x : c[i][f].z) + b0;
                float im = (rr == 0 ? c[i][f].y : c[i][f].w) + b1;
                re = (re > 0.f) ? (re + 1.f) : __expf(re);
                im = (im > 0.f) ? (im + 1.f) : __expf(im);
                int n = m & (Ntok - 1);
                float2 cs = g_rope[(size_t)n * 192 + (jm >> 1)];
                float rre = cs.x * re - cs.y * im;
                float rim = cs.y * re + cs.x * im;
                size_t off = (size_t)m * Cch + jm;
                if (!isK) {
                    *(float2*)&g_qr[off] = make_float2(rre, rim);
                } else {
                    *(float2*)&g_kr[off] = make_float2(rre, rim);
                    ksum_loc[f][0] += re;
                    ksum_loc[f][1] += im;
                }
            }
        }
    }

    if (isK) {
#pragma unroll
        for (int f = 0; f < 4; f++) {
#pragma unroll
            for (int e = 0; e < 2; e++) {
                float v = ksum_loc[f][e];
                v += __shfl_xor_sync(0xffffffffu, v, 4);
                v += __shfl_xor_sync(0xffffffffu, v, 8);
                v += __shfl_xor_sync(0xffffffffu, v, 16);
                if (g == 0) {
                    int jm = (jBase - Cch) + wn * 32 + f * 8 + 2 * l4 + e;
                    atomicAdd(&g_ksum[bb * Cch + jm], v);
                }
            }
        }
    }
}

// ---------------------------------------------------------------------------
// kv[b][h] += (1/N) sum_n outer(k_rope, v);  4 heads/block, 16-way N-split
// grid (16, 3, 16), 256 threads; 64 threads per head, 4x4 microtile, LDS.128
// ---------------------------------------------------------------------------
#define KVCH 32     // n rows per stage

__global__ __launch_bounds__(256) void kv_kernel(const float* __restrict__ x)
{
    int b = blockIdx.x, hq = blockIdx.y, s = blockIdx.z;
    int tid = threadIdx.x;
    __shared__ float ks[KVCH][128];
    __shared__ float vs[KVCH][128];

    int sub = tid >> 6;          // head within quad (0..3)
    int st  = tid & 63;
    int d0  = (st >> 3) * 4;     // 0,4,..,28
    int e0  = (st & 7) * 4;      // 0,4,..,28

    float a[4][4];
#pragma unroll
    for (int r = 0; r < 4; r++)
#pragma unroll
        for (int cc = 0; cc < 4; cc++) a[r][cc] = 0.f;

    int nBase = s * (Ntok / 16);  // 256 tokens per block
    const float* kr = g_kr + ((size_t)b * Ntok + nBase) * Cch + hq * 128;
    const float* vv = x    + ((size_t)b * Ntok + nBase) * Cch + hq * 128;

    // loader coords: 1024 float4 per array / 256 thr = 4 each
    for (int n0 = 0; n0 < Ntok / 16; n0 += KVCH) {
#pragma unroll
        for (int i = 0; i < 4; i++) {
            int idx = tid + i * 256;
            int n = idx >> 5, c4 = (idx & 31) * 4;
            *(float4*)&ks[n][c4] = *(const float4*)(kr + (size_t)(n0 + n) * Cch + c4);
            *(float4*)&vs[n][c4] = *(const float4*)(vv + (size_t)(n0 + n) * Cch + c4);
        }
        __syncthreads();
#pragma unroll 4
        for (int n = 0; n < KVCH; n++) {
            float4 kf = *(float4*)&ks[n][sub * 32 + d0];
            float4 vf = *(float4*)&vs[n][sub * 32 + e0];
            float kk[4] = {kf.x, kf.y, kf.z, kf.w};
            float vvr[4] = {vf.x, vf.y, vf.z, vf.w};
#pragma unroll
            for (int r = 0; r < 4; r++)
#pragma unroll
                for (int cc = 0; cc < 4; cc++) a[r][cc] += kk[r] * vvr[cc];
        }
        __syncthreads();
    }

    const float inv = 1.0f / (float)Ntok;
    float* dst = g_kv + (size_t)(b * NH + hq * 4 + sub) * DH * DH;
#pragma unroll
    for (int r = 0; r < 4; r++)
#pragma unroll
        for (int cc = 0; cc < 4; cc++)
            atomicAdd(&dst[(d0 + r) * DH + e0 + cc], a[r][cc] * inv);
}

// ---------------------------------------------------------------------------
// Finalize: out = (q_rope @ kv[b,h]) * z + dw-conv3x3(x) + bias
// z via rotation invariance: q.k_mean == q_rope . R_n(k_mean)
// head == warp: reductions warp-local. grid (64 rows, 16 batch), 384 threads.
// ---------------------------------------------------------------------------
__global__ __launch_bounds__(384) void finalize_kernel(
    const float* __restrict__ x, const float* __restrict__ lepe_w,
    const float* __restrict__ lepe_b, float* __restrict__ out)
{
    int hh = blockIdx.x, b = blockIdx.y;
    int t = threadIdx.x;
    int h = t >> 5, lane = t & 31;
    bool even = ((t & 1) == 0);

    float km  = g_ksum[b * Cch + t] * (1.0f / (float)Ntok);
    float kmp = __shfl_xor_sync(0xffffffffu, km, 1);   // pair partner

    float wl[9];
#pragma unroll
    for (int i = 0; i < 9; i++) wl[i] = lepe_w[t * 9 + i];
    float lb = lepe_b[t];

    // kv column for this (head, lane): kv[b,h][d][lane]
    float kvcol[DH];
    {
        const float* kvh = g_kv + (size_t)(b * NH + h) * DH * DH;
#pragma unroll
        for (int d = 0; d < DH; d++) kvcol[d] = kvh[d * DH + lane];
    }

    // rolling conv window
    const size_t rowStride = (size_t)HRES * Cch;
    const float* xb = x + (size_t)b * Ntok * Cch + t;
    bool rok[3];
    const float* xr[3];
#pragma unroll
    for (int r = 0; r < 3; r++) {
        int yy = hh - 1 + r;
        rok[r] = (yy >= 0 && yy < HRES);
        xr[r] = xb + (size_t)(rok[r] ? yy : 0) * rowStride;
    }
    float cprev[3], ccur[3], cnext[3];
#pragma unroll
    for (int r = 0; r < 3; r++) {
        cprev[r] = 0.f;
        ccur[r]  = rok[r] ? xr[r][0]          : 0.f;
        cnext[r] = rok[r] ? xr[r][(size_t)Cch] : 0.f;
    }

    const float*  qrrow   = g_qr + ((size_t)b * Ntok + (size_t)hh * HRES) * Cch + t;
    const float2* roperow = g_rope + (size_t)(hh * HRES) * 192 + (t >> 1);
    float* orow = out + ((size_t)b * Ntok + (size_t)hh * HRES) * Cch + t;

    for (int ww = 0; ww < HRES; ww++) {
        size_t g = (size_t)ww * Cch;
        float qrv = qrrow[g];

        // rotated k_mean element for this channel at this token
        float2 cs = roperow[(size_t)ww * 192];
        float rkm = even ? (cs.x * km - cs.y * kmp) : (cs.y * kmp + cs.x * km);

        // z = 1 / (q_rope . R_n(k_mean) + eps)
        float prod = qrv * rkm;
#pragma unroll
        for (int o = 16; o > 0; o >>= 1)
            prod += __shfl_xor_sync(0xffffffffu, prod, o);
        float z = 1.0f / (prod + 1e-6f);

        // q_rope @ kv : broadcast each q_rope[d] within the warp
        float accv = 0.f;
#pragma unroll
        for (int d = 0; d < DH; d++)
            accv += __shfl_sync(0xffffffffu, qrv, d) * kvcol[d];
        float res = accv * z;

        // depthwise 3x3
        float lp = lb;
#pragma unroll
        for (int r = 0; r < 3; r++)
            lp += cprev[r] * wl[r * 3 + 0] + ccur[r] * wl[r * 3 + 1]
                + cnext[r] * wl[r * 3 + 2];

        orow[g] = res + lp;

        // shift window
#pragma unroll
        for (int r = 0; r < 3; r++) { cprev[r] = ccur[r]; ccur[r] = cnext[r]; }
        int xx = ww + 2;
        bool cok = (xx < HRES);
#pragma unroll
        for (int r = 0; r < 3; r++)
            cnext[r] = (rok[r] && cok) ? xr[r][(size_t)xx * Cch] : 0.f;
    }
}

// ---------------------------------------------------------------------------
extern "C" void kernel_launch(void* const* d_in, const int* in_sizes, int n_in,
                              void* d_out, int out_size)
{
    const float* x      = (const float*)d_in[0];
    const float* qk_w   = (const float*)d_in[1];
    const float* qk_b   = (const float*)d_in[2];
    const float* lepe_w = (const float*)d_in[3];
    const float* lepe_b = (const float*)d_in[4];
    float* out = (float*)d_out;

    rope_table_kernel<<<Ntok, 192>>>();
    int zn = Bsz * NH * DH * DH;
    zero_scratch_kernel<<<(zn + 255) / 256, 256>>>();
    gemm_rope_tc<<<dim3(TWOC / BN, (Bsz * Ntok) / BM), 256>>>(x, qk_w, qk_b);
    kv_kernel<<<dim3(Bsz, NH / 4, 16), 256>>>(x);
    finalize_kernel<<<dim3(HRES, Bsz), 384>>>(x, lepe_w, lepe_b, out);
}

// round 4
// speedup vs baseline: 2.6435x; 1.1705x over previous
#include <cuda_runtime.h>
#include <cuda_bf16.h>
#include <cstdint>

#define Bsz 16
#define Ntok 4096
#define Cch 384
#define HRES 64
#define NH 12
#define DH 32
#define TWOC 768

// Scratch (device globals: allocation-free rule)
__device__ float  g_qr[Bsz * Ntok * Cch];   // roped q
__device__ float  g_kr[Bsz * Ntok * Cch];   // roped k
__device__ float  g_ksum[Bsz * Cch];        // sum_n k (unroped)
__device__ float  g_kv  [Bsz * NH * DH * DH];
__device__ float2 g_rope[Ntok * (Cch / 2)]; // cos/sin per (token, pair)

// ---------------------------------------------------------------------------
__global__ void rope_table_kernel() {
    int n = blockIdx.x;          // 0..4095
    int p = threadIdx.x;         // 0..191
    int hh = n >> 6, ww = n & 63;
    int j = (p < 96) ? p : (p - 96);
    float theta = __expf(-((float)j * (1.0f / 96.0f)) * 9.210340371976184f); // 10000^(-j/96)
    float pos = (p < 96) ? (float)hh : (float)ww;
    float s, c;
    sincosf(pos * theta, &s, &c);
    g_rope[(size_t)n * 192 + p] = make_float2(c, s);
}

__global__ void zero_scratch_kernel() {
    int i = blockIdx.x * blockDim.x + threadIdx.x;
    if (i < Bsz * Cch) g_ksum[i] = 0.f;
    if (i < Bsz * NH * DH * DH) g_kv[i] = 0.f;
}

// ---------------------------------------------------------------------------
// helpers
// ---------------------------------------------------------------------------
__device__ __forceinline__ uint32_t packbf(float a, float b) {
    __nv_bfloat162 h = __float22bfloat162_rn(make_float2(a, b));
    return *reinterpret_cast<uint32_t*>(&h);
}

__device__ __forceinline__ void ldm_x4(uint32_t* d, uint32_t addr) {
    asm volatile("ldmatrix.sync.aligned.m8n8.x4.shared.b16 {%0,%1,%2,%3}, [%4];"
                 : "=r"(d[0]), "=r"(d[1]), "=r"(d[2]), "=r"(d[3]) : "r"(addr));
}

__device__ __forceinline__ void mma16(float4& d, const uint32_t* a,
                                      uint32_t b0, uint32_t b1) {
    asm volatile(
        "mma.sync.aligned.m16n8k16.row.col.f32.bf16.bf16.f32 "
        "{%0,%1,%2,%3},{%4,%5,%6,%7},{%8,%9},{%0,%1,%2,%3};\n"
        : "+f"(d.x), "+f"(d.y), "+f"(d.z), "+f"(d.w)
        : "r"(a[0]), "r"(a[1]), "r"(a[2]), "r"(a[3]), "r"(b0), "r"(b1));
}

__device__ __forceinline__ void cp16(uint32_t smem, const void* g) {
    asm volatile("cp.async.cg.shared.global [%0], [%1], 16;" :: "r"(smem), "l"(g));
}

// ---------------------------------------------------------------------------
// GEMM qk = x @ W^T + b via bf16 MMA (m16n8k16 + ldmatrix), fused epilogue.
// BM=128 BN=64 BK=32, 256 threads (8 warps 4x2), warp tile 32x32.
// Register double-buffer over K tiles. grid (12 j-blocks fast, 512 m-blocks).
// ---------------------------------------------------------------------------
#define BM 128
#define BN 64
#define BK 32
#define LDAu 20   // uint32 per smem row (= 40 bf16, 80 bytes)

__global__ __launch_bounds__(256) void gemm_rope_tc(
    const float* __restrict__ x, const float* __restrict__ w,
    const float* __restrict__ bias)
{
    __shared__ uint32_t As[BM * LDAu];   // bf16x2
    __shared__ uint32_t Ws[BN * LDAu];

    int tid  = threadIdx.x;
    int warp = tid >> 5, lane = tid & 31;
    int wm = warp >> 1, wn = warp & 1;
    int g  = lane >> 2, l4 = lane & 3;
    int r8 = lane & 7,  q  = lane >> 3;

    int jBase = blockIdx.x * BN;
    int mBase = blockIdx.y * BM;

    const float* xblk = x + (size_t)mBase * Cch;
    const float* wblk = w + (size_t)jBase * Cch;

    // loader coords
    int am[4], ak[4], wj[2], wk[2];
#pragma unroll
    for (int i = 0; i < 4; i++) { int idx = tid + i * 256; am[i] = idx >> 3; ak[i] = (idx & 7) * 4; }
#pragma unroll
    for (int i = 0; i < 2; i++) { int idx = tid + i * 256; wj[i] = idx >> 3; wk[i] = (idx & 7) * 4; }

    uint32_t asBase = (uint32_t)__cvta_generic_to_shared(As);
    uint32_t wsBase = (uint32_t)__cvta_generic_to_shared(Ws);
    // ldmatrix lane-offsets (bytes): row part * 80 + k-half * 16
    uint32_t aOff = (uint32_t)(((q & 1) * 8 + r8) * 80 + (q >> 1) * 16);
    uint32_t bOff = (uint32_t)(((q >> 1) * 8 + r8) * 80 + (q & 1) * 16);

    float4 c[2][4];
#pragma unroll
    for (int i = 0; i < 2; i++)
#pragma unroll
        for (int f = 0; f < 4; f++) c[i][f] = make_float4(0.f, 0.f, 0.f, 0.f);

    float4 ra[4], rw[2];
#pragma unroll
    for (int i = 0; i < 4; i++) ra[i] = *(const float4*)(xblk + (size_t)am[i] * Cch + ak[i]);
#pragma unroll
    for (int i = 0; i < 2; i++) rw[i] = *(const float4*)(wblk + (size_t)wj[i] * Cch + wk[i]);

    for (int k0 = 0; k0 < Cch; k0 += BK) {
        __syncthreads();   // previous compute done before overwrite
#pragma unroll
        for (int i = 0; i < 4; i++) {
            uint2 u = make_uint2(packbf(ra[i].x, ra[i].y), packbf(ra[i].z, ra[i].w));
            *(uint2*)&As[am[i] * LDAu + (ak[i] >> 1)] = u;
        }
#pragma unroll
        for (int i = 0; i < 2; i++) {
            uint2 u = make_uint2(packbf(rw[i].x, rw[i].y), packbf(rw[i].z, rw[i].w));
            *(uint2*)&Ws[wj[i] * LDAu + (wk[i] >> 1)] = u;
        }
        __syncthreads();

        int kn = k0 + BK;
        if (kn < Cch) {
#pragma unroll
            for (int i = 0; i < 4; i++) ra[i] = *(const float4*)(xblk + (size_t)am[i] * Cch + kn + ak[i]);
#pragma unroll
            for (int i = 0; i < 2; i++) rw[i] = *(const float4*)(wblk + (size_t)wj[i] * Cch + kn + wk[i]);
        }

#pragma unroll
        for (int kk = 0; kk < BK; kk += 16) {
            uint32_t a[2][4], b[2][4];
#pragma unroll
            for (int mi = 0; mi < 2; mi++)
                ldm_x4(a[mi], asBase + (uint32_t)((wm * 32 + mi * 16) * 80 + kk * 2) + aOff);
#pragma unroll
            for (int bg = 0; bg < 2; bg++)
                ldm_x4(b[bg], wsBase + (uint32_t)((wn * 32 + bg * 16) * 80 + kk * 2) + bOff);
#pragma unroll
            for (int mi = 0; mi < 2; mi++)
#pragma unroll
                for (int bg = 0; bg < 2; bg++) {
                    mma16(c[mi][bg * 2],     a[mi], b[bg][0], b[bg][1]);
                    mma16(c[mi][bg * 2 + 1], a[mi], b[bg][2], b[bg][3]);
                }
        }
    }

    // ---- fused epilogue: bias, elu+1, RoPE, k-sum ----
    bool isK = (jBase >= Cch);
    int bb = mBase >> 12;
    float ksum_loc[4][2];
#pragma unroll
    for (int f = 0; f < 4; f++) { ksum_loc[f][0] = 0.f; ksum_loc[f][1] = 0.f; }

#pragma unroll
    for (int i = 0; i < 2; i++) {
        int mrow0 = mBase + wm * 32 + i * 16 + g;
#pragma unroll
        for (int f = 0; f < 4; f++) {
            int j0 = jBase + wn * 32 + f * 8 + 2 * l4;
            int jm = isK ? (j0 - Cch) : j0;
            float b0 = bias[j0], b1 = bias[j0 + 1];
#pragma unroll
            for (int rr = 0; rr < 2; rr++) {
                int m = mrow0 + rr * 8;
                float re = (rr == 0 ? c[i][f].x : c[i][f].z) + b0;
                float im = (rr == 0 ? c[i][f].y : c[i][f].w) + b1;
                re = (re > 0.f) ? (re + 1.f) : __expf(re);
                im = (im > 0.f) ? (im + 1.f) : __expf(im);
                int n = m & (Ntok - 1);
                float2 cs = g_rope[(size_t)n * 192 + (jm >> 1)];
                float rre = cs.x * re - cs.y * im;
                float rim = cs.y * re + cs.x * im;
                size_t off = (size_t)m * Cch + jm;
                if (!isK) {
                    *(float2*)&g_qr[off] = make_float2(rre, rim);
                } else {
                    *(float2*)&g_kr[off] = make_float2(rre, rim);
                    ksum_loc[f][0] += re;
                    ksum_loc[f][1] += im;
                }
            }
        }
    }

    if (isK) {
#pragma unroll
        for (int f = 0; f < 4; f++) {
#pragma unroll
            for (int e = 0; e < 2; e++) {
                float v = ksum_loc[f][e];
                v += __shfl_xor_sync(0xffffffffu, v, 4);
                v += __shfl_xor_sync(0xffffffffu, v, 8);
                v += __shfl_xor_sync(0xffffffffu, v, 16);
                if (g == 0) {
                    int jm = (jBase - Cch) + wn * 32 + f * 8 + 2 * l4 + e;
                    atomicAdd(&g_ksum[bb * Cch + jm], v);
                }
            }
        }
    }
}

// ---------------------------------------------------------------------------
// kv[b][h] += (1/N) sum_n outer(k_rope, v);  4 heads/block, 32-way N-split
// cp.async double-buffered. grid (16, 3, 32), 256 threads, 4x4 microtile.
// ---------------------------------------------------------------------------
#define KVCH 16      // n rows per stage
#define KVSPLIT 32

__global__ __launch_bounds__(256) void kv_kernel(const float* __restrict__ x)
{
    int b = blockIdx.x, hq = blockIdx.y, s = blockIdx.z;
    int tid = threadIdx.x;
    __shared__ float ks[2][KVCH][128];
    __shared__ float vs[2][KVCH][128];

    int sub = tid >> 6;          // head within quad (0..3)
    int st  = tid & 63;
    int d0  = (st >> 3) * 4;
    int e0  = (st & 7) * 4;

    float a[4][4];
#pragma unroll
    for (int r = 0; r < 4; r++)
#pragma unroll
        for (int cc = 0; cc < 4; cc++) a[r][cc] = 0.f;

    const int CHUNK = Ntok / KVSPLIT;      // 128 tokens
    const int STAGES = CHUNK / KVCH;       // 8
    int nBase = s * CHUNK;
    const float* kr = g_kr + ((size_t)b * Ntok + nBase) * Cch + hq * 128;
    const float* vv = x    + ((size_t)b * Ntok + nBase) * Cch + hq * 128;

    // per-thread loader coords: 2 float4 per array per stage
    int ln[2], lc[2];
#pragma unroll
    for (int i = 0; i < 2; i++) { int idx = tid + i * 256; ln[i] = idx >> 5; lc[i] = (idx & 31) * 4; }
    uint32_t ksB = (uint32_t)__cvta_generic_to_shared(&ks[0][0][0]);
    uint32_t vsB = (uint32_t)__cvta_generic_to_shared(&vs[0][0][0]);

    auto load_stage = [&](int stg, int buf) {
#pragma unroll
        for (int i = 0; i < 2; i++) {
            uint32_t so = (uint32_t)(((buf * KVCH + ln[i]) * 128 + lc[i]) * 4);
            size_t go = (size_t)(stg * KVCH + ln[i]) * Cch + lc[i];
            cp16(ksB + so, kr + go);
            cp16(vsB + so, vv + go);
        }
        asm volatile("cp.async.commit_group;");
    };

    load_stage(0, 0);
    for (int stg = 0; stg < STAGES; stg++) {
        if (stg + 1 < STAGES) {
            load_stage(stg + 1, (stg + 1) & 1);
            asm volatile("cp.async.wait_group 1;");
        } else {
            asm volatile("cp.async.wait_group 0;");
        }
        __syncthreads();
        int buf = stg & 1;
#pragma unroll
        for (int n = 0; n < KVCH; n++) {
            float4 kf = *(float4*)&ks[buf][n][sub * 32 + d0];
            float4 vf = *(float4*)&vs[buf][n][sub * 32 + e0];
            float kk[4] = {kf.x, kf.y, kf.z, kf.w};
            float vvr[4] = {vf.x, vf.y, vf.z, vf.w};
#pragma unroll
            for (int r = 0; r < 4; r++)
#pragma unroll
                for (int cc = 0; cc < 4; cc++) a[r][cc] += kk[r] * vvr[cc];
        }
        __syncthreads();
    }

    const float inv = 1.0f / (float)Ntok;
    float* dst = g_kv + (size_t)(b * NH + hq * 4 + sub) * DH * DH;
#pragma unroll
    for (int r = 0; r < 4; r++)
#pragma unroll
        for (int cc = 0; cc < 4; cc++)
            atomicAdd(&dst[(d0 + r) * DH + e0 + cc], a[r][cc] * inv);
}

// ---------------------------------------------------------------------------
// Finalize: out = (q_rope @ kv[b,h]) * z + dw-conv3x3(x) + bias
// z via rotation invariance: q.k_mean == q_rope . R_n(k_mean)
// head == warp: reductions warp-local. grid (64 rows, 16 batch), 384 threads.
// ---------------------------------------------------------------------------
__global__ __launch_bounds__(384) void finalize_kernel(
    const float* __restrict__ x, const float* __restrict__ lepe_w,
    const float* __restrict__ lepe_b, float* __restrict__ out)
{
    int hh = blockIdx.x, b = blockIdx.y;
    int t = threadIdx.x;
    int h = t >> 5, lane = t & 31;
    bool even = ((t & 1) == 0);

    float km  = g_ksum[b * Cch + t] * (1.0f / (float)Ntok);
    float kmp = __shfl_xor_sync(0xffffffffu, km, 1);   // pair partner

    float wl[9];
#pragma unroll
    for (int i = 0; i < 9; i++) wl[i] = lepe_w[t * 9 + i];
    float lb = lepe_b[t];

    float kvcol[DH];
    {
        const float* kvh = g_kv + (size_t)(b * NH + h) * DH * DH;
#pragma unroll
        for (int d = 0; d < DH; d++) kvcol[d] = kvh[d * DH + lane];
    }

    const size_t rowStride = (size_t)HRES * Cch;
    const float* xb = x + (size_t)b * Ntok * Cch + t;
    bool rok[3];
    const float* xr[3];
#pragma unroll
    for (int r = 0; r < 3; r++) {
        int yy = hh - 1 + r;
        rok[r] = (yy >= 0 && yy < HRES);
        xr[r] = xb + (size_t)(rok[r] ? yy : 0) * rowStride;
    }
    float cprev[3], ccur[3], cnext[3];
#pragma unroll
    for (int r = 0; r < 3; r++) {
        cprev[r] = 0.f;
        ccur[r]  = rok[r] ? xr[r][0]          : 0.f;
        cnext[r] = rok[r] ? xr[r][(size_t)Cch] : 0.f;
    }

    const float*  qrrow   = g_qr + ((size_t)b * Ntok + (size_t)hh * HRES) * Cch + t;
    const float2* roperow = g_rope + (size_t)(hh * HRES) * 192 + (t >> 1);
    float* orow = out + ((size_t)b * Ntok + (size_t)hh * HRES) * Cch + t;

    for (int ww = 0; ww < HRES; ww++) {
        size_t g = (size_t)ww * Cch;
        float qrv = qrrow[g];

        float2 cs = roperow[(size_t)ww * 192];
        float rkm = even ? (cs.x * km - cs.y * kmp) : (cs.y * kmp + cs.x * km);

        float prod = qrv * rkm;
#pragma unroll
        for (int o = 16; o > 0; o >>= 1)
            prod += __shfl_xor_sync(0xffffffffu, prod, o);
        float z = 1.0f / (prod + 1e-6f);

        float accv = 0.f;
#pragma unroll
        for (int d = 0; d < DH; d++)
            accv += __shfl_sync(0xffffffffu, qrv, d) * kvcol[d];
        float res = accv * z;

        float lp = lb;
#pragma unroll
        for (int r = 0; r < 3; r++)
            lp += cprev[r] * wl[r * 3 + 0] + ccur[r] * wl[r * 3 + 1]
                + cnext[r] * wl[r * 3 + 2];

        orow[g] = res + lp;

#pragma unroll
        for (int r = 0; r < 3; r++) { cprev[r] = ccur[r]; ccur[r] = cnext[r]; }
        int xx = ww + 2;
        bool cok = (xx < HRES);
#pragma unroll
        for (int r = 0; r < 3; r++)
            cnext[r] = (rok[r] && cok) ? xr[r][(size_t)xx * Cch] : 0.f;
    }
}

// ---------------------------------------------------------------------------
extern "C" void kernel_launch(void* const* d_in, const int* in_sizes, int n_in,
                              void* d_out, int out_size)
{
    const float* x      = (const float*)d_in[0];
    const float* qk_w   = (const float*)d_in[1];
    const float* qk_b   = (const float*)d_in[2];
    const float* lepe_w = (const float*)d_in[3];
    const float* lepe_b = (const float*)d_in[4];
    float* out = (float*)d_out;

    rope_table_kernel<<<Ntok, 192>>>();
    int zn = Bsz * NH * DH * DH;
    zero_scratch_kernel<<<(zn + 255) / 256, 256>>>();
    gemm_rope_tc<<<dim3(TWOC / BN, (Bsz * Ntok) / BM), 256>>>(x, qk_w, qk_b);
    kv_kernel<<<dim3(Bsz, NH / 4, KVSPLIT), 256>>>(x);
    finalize_kernel<<<dim3(HRES, Bsz), 384>>>(x, lepe_w, lepe_b, out);
}

// round 5
// speedup vs baseline: 3.0473x; 1.1527x over previous
#include <cuda_runtime.h>
#include <cuda_bf16.h>
#include <cstdint>

#define Bsz 16
#define Ntok 4096
#define Cch 384
#define HRES 64
#define NH 12
#define DH 32
#define TWOC 768

// Scratch (device globals: allocation-free rule)
__device__ __nv_bfloat16 g_xbf[Bsz * Ntok * Cch];   // bf16 copy of x
__device__ __nv_bfloat16 g_wbf[TWOC * Cch];         // bf16 copy of qk_w
__device__ __nv_bfloat16 g_qrb[Bsz * Ntok * Cch];   // roped q (bf16)
__device__ __nv_bfloat16 g_krb[Bsz * Ntok * Cch];   // roped k (bf16)
__device__ float  g_ksum[Bsz * Cch];                // sum_n k (unroped, fp32)
__device__ float  g_kv  [Bsz * NH * DH * DH];
__device__ float2 g_rope[Ntok * (Cch / 2)];

// ---------------------------------------------------------------------------
__global__ void rope_table_kernel() {
    int n = blockIdx.x;          // 0..4095
    int p = threadIdx.x;         // 0..191
    int hh = n >> 6, ww = n & 63;
    int j = (p < 96) ? p : (p - 96);
    float theta = __expf(-((float)j * (1.0f / 96.0f)) * 9.210340371976184f);
    float pos = (p < 96) ? (float)hh : (float)ww;
    float s, c;
    sincosf(pos * theta, &s, &c);
    g_rope[(size_t)n * 192 + p] = make_float2(c, s);
}

__global__ void zero_scratch_kernel() {
    int i = blockIdx.x * blockDim.x + threadIdx.x;
    if (i < Bsz * Cch) g_ksum[i] = 0.f;
    if (i < Bsz * NH * DH * DH) g_kv[i] = 0.f;
}

// ---------------------------------------------------------------------------
__device__ __forceinline__ uint32_t packbf(float a, float b) {
    __nv_bfloat162 h = __float22bfloat162_rn(make_float2(a, b));
    return *reinterpret_cast<uint32_t*>(&h);
}

__device__ __forceinline__ void ldm_x4(uint32_t* d, uint32_t addr) {
    asm volatile("ldmatrix.sync.aligned.m8n8.x4.shared.b16 {%0,%1,%2,%3}, [%4];"
                 : "=r"(d[0]), "=r"(d[1]), "=r"(d[2]), "=r"(d[3]) : "r"(addr));
}

__device__ __forceinline__ void mma16(float4& d, const uint32_t* a,
                                      uint32_t b0, uint32_t b1) {
    asm volatile(
        "mma.sync.aligned.m16n8k16.row.col.f32.bf16.bf16.f32 "
        "{%0,%1,%2,%3},{%4,%5,%6,%7},{%8,%9},{%0,%1,%2,%3};\n"
        : "+f"(d.x), "+f"(d.y), "+f"(d.z), "+f"(d.w)
        : "r"(a[0]), "r"(a[1]), "r"(a[2]), "r"(a[3]), "r"(b0), "r"(b1));
}

__device__ __forceinline__ void cp16(uint32_t smem, const void* g) {
    asm volatile("cp.async.cg.shared.global [%0], [%1], 16;" :: "r"(smem), "l"(g));
}

// ---------------------------------------------------------------------------
// Convert x and qk_w to bf16 (one pass).
// blocks [0, 12288): x (8 elems/thread). blocks [12288, ...): w.
// ---------------------------------------------------------------------------
#define XBLK 12288
__global__ __launch_bounds__(256) void convert_kernel(
    const float* __restrict__ x, const float* __restrict__ w)
{
    if (blockIdx.x < XBLK) {
        size_t o = ((size_t)blockIdx.x * 256 + threadIdx.x) * 8;
        float4 a = *(const float4*)(x + o);
        float4 b = *(const float4*)(x + o + 4);
        uint4 u = make_uint4(packbf(a.x, a.y), packbf(a.z, a.w),
                             packbf(b.x, b.y), packbf(b.z, b.w));
        *(uint4*)&g_xbf[o] = u;
    } else {
        size_t o = ((size_t)(blockIdx.x - XBLK) * 256 + threadIdx.x) * 8;
        if (o < (size_t)TWOC * Cch) {
            float4 a = *(const float4*)(w + o);
            float4 b = *(const float4*)(w + o + 4);
            uint4 u = make_uint4(packbf(a.x, a.y), packbf(a.z, a.w),
                                 packbf(b.x, b.y), packbf(b.z, b.w));
            *(uint4*)&g_wbf[o] = u;
        }
    }
}

// ---------------------------------------------------------------------------
// GEMM qk = x @ W^T + b via bf16 MMA, cp.async 3-stage pipeline.
// BM=128 BN=64 BK=32, 256 threads (8 warps 4x2), warp tile 32x32.
// Epilogue: bias, elu+1, RoPE, k-sum; outputs bf16.
// grid (12 j-blocks fast, 512 m-blocks) -> A tiles shared across j via L2.
// ---------------------------------------------------------------------------
#define BM 128
#define BN 64
#define BK 32
#define STAGES 3
#define NKT (Cch / BK)          // 12
#define AROW 80                  // bytes per smem row (40 bf16)
#define ATILE (BM * AROW)        // 10240
#define WTILE (BN * AROW)        // 5120

__global__ __launch_bounds__(256) void gemm_rope_tc(const float* __restrict__ bias)
{
    __shared__ __align__(16) uint8_t smA[STAGES * ATILE];
    __shared__ __align__(16) uint8_t smW[STAGES * WTILE];

    int tid  = threadIdx.x;
    int warp = tid >> 5, lane = tid & 31;
    int wm = warp >> 1, wn = warp & 1;
    int g  = lane >> 2, l4 = lane & 3;
    int r8 = lane & 7,  q  = lane >> 3;

    int jBase = blockIdx.x * BN;
    int mBase = blockIdx.y * BM;

    const __nv_bfloat16* xblk = g_xbf + (size_t)mBase * Cch;
    const __nv_bfloat16* wblk = g_wbf + (size_t)jBase * Cch;

    // loader coords: A 512 chunks (2/thr), W 256 chunks (1/thr); chunk = 8 bf16
    int am[2], ak[2];
#pragma unroll
    for (int i = 0; i < 2; i++) { int idx = tid + i * 256; am[i] = idx >> 2; ak[i] = (idx & 3) * 8; }
    int wj = tid >> 2, wk = (tid & 3) * 8;

    uint32_t aBase = (uint32_t)__cvta_generic_to_shared(smA);
    uint32_t wBase = (uint32_t)__cvta_generic_to_shared(smW);
    uint32_t aOff = (uint32_t)(((q & 1) * 8 + r8) * AROW + (q >> 1) * 16);
    uint32_t bOff = (uint32_t)(((q >> 1) * 8 + r8) * AROW + (q & 1) * 16);

    auto loadTile = [&](int t, int buf) {
        int k0 = t * BK;
#pragma unroll
        for (int i = 0; i < 2; i++)
            cp16(aBase + (uint32_t)(buf * ATILE + am[i] * AROW + ak[i] * 2),
                 xblk + (size_t)am[i] * Cch + k0 + ak[i]);
        cp16(wBase + (uint32_t)(buf * WTILE + wj * AROW + wk * 2),
             wblk + (size_t)wj * Cch + k0 + wk);
        asm volatile("cp.async.commit_group;");
    };

    float4 c[2][4];
#pragma unroll
    for (int i = 0; i < 2; i++)
#pragma unroll
        for (int f = 0; f < 4; f++) c[i][f] = make_float4(0.f, 0.f, 0.f, 0.f);

    loadTile(0, 0);
    loadTile(1, 1);

    for (int t = 0; t < NKT; t++) {
        asm volatile("cp.async.wait_group 1;");
        __syncthreads();
        if (t + 2 < NKT) loadTile(t + 2, (t + 2) % STAGES);

        int buf = t % STAGES;
        uint32_t aT = aBase + (uint32_t)(buf * ATILE);
        uint32_t wT = wBase + (uint32_t)(buf * WTILE);
#pragma unroll
        for (int kk = 0; kk < BK; kk += 16) {
            uint32_t a[2][4], b[2][4];
#pragma unroll
            for (int mi = 0; mi < 2; mi++)
                ldm_x4(a[mi], aT + (uint32_t)((wm * 32 + mi * 16) * AROW + kk * 2) + aOff);
#pragma unroll
            for (int bg = 0; bg < 2; bg++)
                ldm_x4(b[bg], wT + (uint32_t)((wn * 32 + bg * 16) * AROW + kk * 2) + bOff);
#pragma unroll
            for (int mi = 0; mi < 2; mi++)
#pragma unroll
                for (int bg = 0; bg < 2; bg++) {
                    mma16(c[mi][bg * 2],     a[mi], b[bg][0], b[bg][1]);
                    mma16(c[mi][bg * 2 + 1], a[mi], b[bg][2], b[bg][3]);
                }
        }
    }

    // ---- fused epilogue ----
    bool isK = (jBase >= Cch);
    int bb = mBase >> 12;
    float ksum_loc[4][2];
#pragma unroll
    for (int f = 0; f < 4; f++) { ksum_loc[f][0] = 0.f; ksum_loc[f][1] = 0.f; }

#pragma unroll
    for (int i = 0; i < 2; i++) {
        int mrow0 = mBase + wm * 32 + i * 16 + g;
#pragma unroll
        for (int f = 0; f < 4; f++) {
            int j0 = jBase + wn * 32 + f * 8 + 2 * l4;
            int jm = isK ? (j0 - Cch) : j0;
            float b0 = bias[j0], b1 = bias[j0 + 1];
#pragma unroll
            for (int rr = 0; rr < 2; rr++) {
                int m = mrow0 + rr * 8;
                float re = (rr == 0 ? c[i][f].x : c[i][f].z) + b0;
                float im = (rr == 0 ? c[i][f].y : c[i][f].w) + b1;
                re = (re > 0.f) ? (re + 1.f) : __expf(re);
                im = (im > 0.f) ? (im + 1.f) : __expf(im);
                int n = m & (Ntok - 1);
                float2 cs = g_rope[(size_t)n * 192 + (jm >> 1)];
                float rre = cs.x * re - cs.y * im;
                float rim = cs.y * re + cs.x * im;
                size_t off = (size_t)m * Cch + jm;
                uint32_t pk = packbf(rre, rim);
                if (!isK) {
                    *(uint32_t*)&g_qrb[off] = pk;
                } else {
                    *(uint32_t*)&g_krb[off] = pk;
                    ksum_loc[f][0] += re;
                    ksum_loc[f][1] += im;
                }
            }
        }
    }

    if (isK) {
#pragma unroll
        for (int f = 0; f < 4; f++) {
#pragma unroll
            for (int e = 0; e < 2; e++) {
                float v = ksum_loc[f][e];
                v += __shfl_xor_sync(0xffffffffu, v, 4);
                v += __shfl_xor_sync(0xffffffffu, v, 8);
                v += __shfl_xor_sync(0xffffffffu, v, 16);
                if (g == 0) {
                    int jm = (jBase - Cch) + wn * 32 + f * 8 + 2 * l4 + e;
                    atomicAdd(&g_ksum[bb * Cch + jm], v);
                }
            }
        }
    }
}

// ---------------------------------------------------------------------------
// kv[b][h] += (1/N) sum_n outer(k_rope, v);  bf16 inputs, fp32 accumulate.
// 4 heads/block, 32-way N-split, cp.async double-buffer.
// grid (16, 3, 32), 256 threads, 4x4 microtile.
// ---------------------------------------------------------------------------
#define KVCH 32      // n rows per stage
#define KVSPLIT 32
#define KVROW 256    // bytes per smem row (128 bf16)
#define KVTILE (KVCH * KVROW)   // 8192

__global__ __launch_bounds__(256) void kv_kernel()
{
    int b = blockIdx.x, hq = blockIdx.y, s = blockIdx.z;
    int tid = threadIdx.x;
    __shared__ __align__(16) uint8_t ksm[2 * KVTILE];
    __shared__ __align__(16) uint8_t vsm[2 * KVTILE];

    int sub = tid >> 6;
    int st  = tid & 63;
    int d0  = (st >> 3) * 4;
    int e0  = (st & 7) * 4;

    float a[4][4];
#pragma unroll
    for (int r = 0; r < 4; r++)
#pragma unroll
        for (int cc = 0; cc < 4; cc++) a[r][cc] = 0.f;

    const int CHUNK = Ntok / KVSPLIT;      // 128 tokens
    const int NSTG  = CHUNK / KVCH;        // 4
    int nBase = s * CHUNK;
    const __nv_bfloat16* kr = g_krb + ((size_t)b * Ntok + nBase) * Cch + hq * 128;
    const __nv_bfloat16* vv = g_xbf + ((size_t)b * Ntok + nBase) * Cch + hq * 128;

    // loaders: per array per stage 512 chunks of 8 bf16 -> 2 per thread
    int ln[2], lc[2];
#pragma unroll
    for (int i = 0; i < 2; i++) { int idx = tid + i * 256; ln[i] = idx >> 4; lc[i] = (idx & 15) * 8; }
    uint32_t ksB = (uint32_t)__cvta_generic_to_shared(ksm);
    uint32_t vsB = (uint32_t)__cvta_generic_to_shared(vsm);

    auto load_stage = [&](int stg, int buf) {
#pragma unroll
        for (int i = 0; i < 2; i++) {
            uint32_t so = (uint32_t)(buf * KVTILE + ln[i] * KVROW + lc[i] * 2);
            size_t go = (size_t)(stg * KVCH + ln[i]) * Cch + lc[i];
            cp16(ksB + so, kr + go);
            cp16(vsB + so, vv + go);
        }
        asm volatile("cp.async.commit_group;");
    };

    load_stage(0, 0);
    for (int stg = 0; stg < NSTG; stg++) {
        if (stg + 1 < NSTG) {
            load_stage(stg + 1, (stg + 1) & 1);
            asm volatile("cp.async.wait_group 1;");
        } else {
            asm volatile("cp.async.wait_group 0;");
        }
        __syncthreads();
        int buf = stg & 1;
        const uint8_t* kb = ksm + buf * KVTILE + (sub * 32 + d0) * 2;
        const uint8_t* vb = vsm + buf * KVTILE + (sub * 32 + e0) * 2;
#pragma unroll
        for (int n = 0; n < KVCH; n++) {
            const __nv_bfloat162* kp = (const __nv_bfloat162*)(kb + n * KVROW);
            const __nv_bfloat162* vp = (const __nv_bfloat162*)(vb + n * KVROW);
            float2 k01 = __bfloat1622float2(kp[0]);
            float2 k23 = __bfloat1622float2(kp[1]);
            float2 v01 = __bfloat1622float2(vp[0]);
            float2 v23 = __bfloat1622float2(vp[1]);
            float kk[4] = {k01.x, k01.y, k23.x, k23.y};
            float vr[4] = {v01.x, v01.y, v23.x, v23.y};
#pragma unroll
            for (int r = 0; r < 4; r++)
#pragma unroll
                for (int cc = 0; cc < 4; cc++) a[r][cc] += kk[r] * vr[cc];
        }
        __syncthreads();
    }

    const float inv = 1.0f / (float)Ntok;
    float* dst = g_kv + (size_t)(b * NH + hq * 4 + sub) * DH * DH;
#pragma unroll
    for (int r = 0; r < 4; r++)
#pragma unroll
        for (int cc = 0; cc < 4; cc++)
            atomicAdd(&dst[(d0 + r) * DH + e0 + cc], a[r][cc] * inv);
}

// ---------------------------------------------------------------------------
// Finalize: out = (q_rope @ kv[b,h]) * z + dw-conv3x3(x) + bias
// z via rotation invariance: q.k_mean == q_rope . R_n(k_mean)
// head == warp. grid (64 rows, 16 batch), 384 threads.
// ---------------------------------------------------------------------------
__global__ __launch_bounds__(384) void finalize_kernel(
    const float* __restrict__ x, const float* __restrict__ lepe_w,
    const float* __restrict__ lepe_b, float* __restrict__ out)
{
    int hh = blockIdx.x, b = blockIdx.y;
    int t = threadIdx.x;
    int h = t >> 5, lane = t & 31;
    bool even = ((t & 1) == 0);

    float km  = g_ksum[b * Cch + t] * (1.0f / (float)Ntok);
    float kmp = __shfl_xor_sync(0xffffffffu, km, 1);

    float wl[9];
#pragma unroll
    for (int i = 0; i < 9; i++) wl[i] = lepe_w[t * 9 + i];
    float lb = lepe_b[t];

    float kvcol[DH];
    {
        const float* kvh = g_kv + (size_t)(b * NH + h) * DH * DH;
#pragma unroll
        for (int d = 0; d < DH; d++) kvcol[d] = kvh[d * DH + lane];
    }

    const size_t rowStride = (size_t)HRES * Cch;
    const float* xb = x + (size_t)b * Ntok * Cch + t;
    bool rok[3];
    const float* xr[3];
#pragma unroll
    for (int r = 0; r < 3; r++) {
        int yy = hh - 1 + r;
        rok[r] = (yy >= 0 && yy < HRES);
        xr[r] = xb + (size_t)(rok[r] ? yy : 0) * rowStride;
    }
    float cprev[3], ccur[3], cnext[3];
#pragma unroll
    for (int r = 0; r < 3; r++) {
        cprev[r] = 0.f;
        ccur[r]  = rok[r] ? xr[r][0]          : 0.f;
        cnext[r] = rok[r] ? xr[r][(size_t)Cch] : 0.f;
    }

    const __nv_bfloat16* qrrow = g_qrb + ((size_t)b * Ntok + (size_t)hh * HRES) * Cch + t;
    const float2* roperow = g_rope + (size_t)(hh * HRES) * 192 + (t >> 1);
    float* orow = out + ((size_t)b * Ntok + (size_t)hh * HRES) * Cch + t;

    for (int ww = 0; ww < HRES; ww++) {
        size_t g = (size_t)ww * Cch;
        float qrv = __bfloat162float(qrrow[g]);

        float2 cs = roperow[(size_t)ww * 192];
        float rkm = even ? (cs.x * km - cs.y * kmp) : (cs.y * kmp + cs.x * km);

        float prod = qrv * rkm;
#pragma unroll
        for (int o = 16; o > 0; o >>= 1)
            prod += __shfl_xor_sync(0xffffffffu, prod, o);
        float z = 1.0f / (prod + 1e-6f);

        float accv = 0.f;
#pragma unroll
        for (int d = 0; d < DH; d++)
            accv += __shfl_sync(0xffffffffu, qrv, d) * kvcol[d];
        float res = accv * z;

        float lp = lb;
#pragma unroll
        for (int r = 0; r < 3; r++)
            lp += cprev[r] * wl[r * 3 + 0] + ccur[r] * wl[r * 3 + 1]
                + cnext[r] * wl[r * 3 + 2];

        orow[g] = res + lp;

#pragma unroll
        for (int r = 0; r < 3; r++) { cprev[r] = ccur[r]; ccur[r] = cnext[r]; }
        int xx = ww + 2;
        bool cok = (xx < HRES);
#pragma unroll
        for (int r = 0; r < 3; r++)
            cnext[r] = (rok[r] && cok) ? xr[r][(size_t)xx * Cch] : 0.f;
    }
}

// ---------------------------------------------------------------------------
extern "C" void kernel_launch(void* const* d_in, const int* in_sizes, int n_in,
                              void* d_out, int out_size)
{
    const float* x      = (const float*)d_in[0];
    const float* qk_w   = (const float*)d_in[1];
    const float* qk_b   = (const float*)d_in[2];
    const float* lepe_w = (const float*)d_in[3];
    const float* lepe_b = (const float*)d_in[4];
    float* out = (float*)d_out;

    rope_table_kernel<<<Ntok, 192>>>();
    int zn = Bsz * NH * DH * DH;
    zero_scratch_kernel<<<(zn + 255) / 256, 256>>>();
    int wblk = ((TWOC * Cch) / 8 + 255) / 256;           // 144
    convert_kernel<<<XBLK + wblk, 256>>>(x, qk_w);
    gemm_rope_tc<<<dim3(TWOC / BN, (Bsz * Ntok) / BM), 256>>>(qk_b);
    kv_kernel<<<dim3(Bsz, NH / 4, KVSPLIT), 256>>>();
    finalize_kernel<<<dim3(HRES, Bsz), 384>>>(x, lepe_w, lepe_b, out);
}

// round 6
// speedup vs baseline: 3.5090x; 1.1515x over previous
#include <cuda_runtime.h>
#include <cuda_bf16.h>
#include <cstdint>

#define Bsz 16
#define Ntok 4096
#define Cch 384
#define HRES 64
#define NH 12
#define DH 32
#define TWOC 768

// Scratch (device globals: allocation-free rule)
__device__ __nv_bfloat16 g_xbf[Bsz * Ntok * Cch];   // bf16 copy of x
__device__ __nv_bfloat16 g_wbf[TWOC * Cch];         // bf16 copy of qk_w
__device__ __nv_bfloat16 g_qrb[Bsz * Ntok * Cch];   // roped q (bf16)
__device__ __nv_bfloat16 g_krb[Bsz * Ntok * Cch];   // roped k (bf16)
__device__ float  g_ksum[Bsz * Cch];                // sum_n k (unroped, fp32)
__device__ float  g_kv  [Bsz * NH * DH * DH];
__device__ float2 g_rope[Ntok * (Cch / 2)];

// ---------------------------------------------------------------------------
__global__ void rope_table_kernel() {
    int n = blockIdx.x;
    int p = threadIdx.x;
    int hh = n >> 6, ww = n & 63;
    int j = (p < 96) ? p : (p - 96);
    float theta = __expf(-((float)j * (1.0f / 96.0f)) * 9.210340371976184f);
    float pos = (p < 96) ? (float)hh : (float)ww;
    float s, c;
    sincosf(pos * theta, &s, &c);
    g_rope[(size_t)n * 192 + p] = make_float2(c, s);
}

__global__ void zero_scratch_kernel() {
    int i = blockIdx.x * blockDim.x + threadIdx.x;
    if (i < Bsz * Cch) g_ksum[i] = 0.f;
    if (i < Bsz * NH * DH * DH) g_kv[i] = 0.f;
}

// ---------------------------------------------------------------------------
__device__ __forceinline__ uint32_t packbf(float a, float b) {
    __nv_bfloat162 h = __float22bfloat162_rn(make_float2(a, b));
    return *reinterpret_cast<uint32_t*>(&h);
}

__device__ __forceinline__ void ldm_x4(uint32_t* d, uint32_t addr) {
    asm volatile("ldmatrix.sync.aligned.m8n8.x4.shared.b16 {%0,%1,%2,%3}, [%4];"
                 : "=r"(d[0]), "=r"(d[1]), "=r"(d[2]), "=r"(d[3]) : "r"(addr));
}

__device__ __forceinline__ void mma16(float4& d, const uint32_t* a,
                                      uint32_t b0, uint32_t b1) {
    asm volatile(
        "mma.sync.aligned.m16n8k16.row.col.f32.bf16.bf16.f32 "
        "{%0,%1,%2,%3},{%4,%5,%6,%7},{%8,%9},{%0,%1,%2,%3};\n"
        : "+f"(d.x), "+f"(d.y), "+f"(d.z), "+f"(d.w)
        : "r"(a[0]), "r"(a[1]), "r"(a[2]), "r"(a[3]), "r"(b0), "r"(b1));
}

__device__ __forceinline__ void cp16(uint32_t smem, const void* g) {
    asm volatile("cp.async.cg.shared.global [%0], [%1], 16;" :: "r"(smem), "l"(g));
}

// ---------------------------------------------------------------------------
// Convert x and qk_w to bf16 (one pass).
// ---------------------------------------------------------------------------
#define XBLK 12288
__global__ __launch_bounds__(256) void convert_kernel(
    const float* __restrict__ x, const float* __restrict__ w)
{
    if (blockIdx.x < XBLK) {
        size_t o = ((size_t)blockIdx.x * 256 + threadIdx.x) * 8;
        float4 a = *(const float4*)(x + o);
        float4 b = *(const float4*)(x + o + 4);
        uint4 u = make_uint4(packbf(a.x, a.y), packbf(a.z, a.w),
                             packbf(b.x, b.y), packbf(b.z, b.w));
        *(uint4*)&g_xbf[o] = u;
    } else {
        size_t o = ((size_t)(blockIdx.x - XBLK) * 256 + threadIdx.x) * 8;
        if (o < (size_t)TWOC * Cch) {
            float4 a = *(const float4*)(w + o);
            float4 b = *(const float4*)(w + o + 4);
            uint4 u = make_uint4(packbf(a.x, a.y), packbf(a.z, a.w),
                                 packbf(b.x, b.y), packbf(b.z, b.w));
            *(uint4*)&g_wbf[o] = u;
        }
    }
}

// ---------------------------------------------------------------------------
// GEMM qk = x @ W^T + b via bf16 MMA, cp.async 3-stage pipeline.
// BM=128 BN=128 BK=32, 256 threads (8 warps: 2 in M x 4 in N), warp 64x32.
// grid (6 j-blocks fast, 512 m-blocks).
// ---------------------------------------------------------------------------
#define BM 128
#define BN 128
#define BK 32
#define STAGES 3
#define NKT (Cch / BK)          // 12
#define AROW 80                  // bytes per smem row (40 bf16)
#define ATILE (BM * AROW)        // 10240
#define WTILE (BN * AROW)        // 10240
#define GEMM_SMEM (STAGES * (ATILE + WTILE))   // 61440

__global__ __launch_bounds__(256, 2) void gemm_rope_tc(const float* __restrict__ bias)
{
    extern __shared__ __align__(16) uint8_t gsm[];
    uint8_t* smA = gsm;
    uint8_t* smW = gsm + STAGES * ATILE;

    int tid  = threadIdx.x;
    int warp = tid >> 5, lane = tid & 31;
    int wm = warp >> 2, wn = warp & 3;
    int g  = lane >> 2, l4 = lane & 3;
    int r8 = lane & 7,  qq = lane >> 3;

    int jBase = blockIdx.x * BN;
    int mBase = blockIdx.y * BM;

    const __nv_bfloat16* xblk = g_xbf + (size_t)mBase * Cch;
    const __nv_bfloat16* wblk = g_wbf + (size_t)jBase * Cch;

    // loader coords: 512 chunks per tile (A and W each), 2 per thread
    int am[2], ak[2];
#pragma unroll
    for (int i = 0; i < 2; i++) { int idx = tid + i * 256; am[i] = idx >> 2; ak[i] = (idx & 3) * 8; }

    uint32_t aBase = (uint32_t)__cvta_generic_to_shared(smA);
    uint32_t wBase = (uint32_t)__cvta_generic_to_shared(smW);
    uint32_t aOff = (uint32_t)(((qq & 1) * 8 + r8) * AROW + (qq >> 1) * 16);
    uint32_t bOff = (uint32_t)(((qq >> 1) * 8 + r8) * AROW + (qq & 1) * 16);

    auto loadTile = [&](int t, int buf) {
        int k0 = t * BK;
#pragma unroll
        for (int i = 0; i < 2; i++) {
            cp16(aBase + (uint32_t)(buf * ATILE + am[i] * AROW + ak[i] * 2),
                 xblk + (size_t)am[i] * Cch + k0 + ak[i]);
            cp16(wBase + (uint32_t)(buf * WTILE + am[i] * AROW + ak[i] * 2),
                 wblk + (size_t)am[i] * Cch + k0 + ak[i]);
        }
        asm volatile("cp.async.commit_group;");
    };

    float4 c[4][4];
#pragma unroll
    for (int i = 0; i < 4; i++)
#pragma unroll
        for (int f = 0; f < 4; f++) c[i][f] = make_float4(0.f, 0.f, 0.f, 0.f);

    loadTile(0, 0);
    loadTile(1, 1);

    for (int t = 0; t < NKT; t++) {
        asm volatile("cp.async.wait_group 1;");
        __syncthreads();
        if (t + 2 < NKT) loadTile(t + 2, (t + 2) % STAGES);

        int buf = t % STAGES;
        uint32_t aT = aBase + (uint32_t)(buf * ATILE);
        uint32_t wT = wBase + (uint32_t)(buf * WTILE);
#pragma unroll
        for (int kk = 0; kk < BK; kk += 16) {
            uint32_t a[4][4], b[2][4];
#pragma unroll
            for (int mi = 0; mi < 4; mi++)
                ldm_x4(a[mi], aT + (uint32_t)((wm * 64 + mi * 16) * AROW + kk * 2) + aOff);
#pragma unroll
            for (int bg = 0; bg < 2; bg++)
                ldm_x4(b[bg], wT + (uint32_t)((wn * 32 + bg * 16) * AROW + kk * 2) + bOff);
#pragma unroll
            for (int mi = 0; mi < 4; mi++)
#pragma unroll
                for (int bg = 0; bg < 2; bg++) {
                    mma16(c[mi][bg * 2],     a[mi], b[bg][0], b[bg][1]);
                    mma16(c[mi][bg * 2 + 1], a[mi], b[bg][2], b[bg][3]);
                }
        }
    }

    // ---- fused epilogue: bias, elu+1, RoPE, k-sum; bf16 outputs ----
    bool isK = (jBase >= Cch);
    int bb = mBase >> 12;
    float ksum_loc[4][2];
#pragma unroll
    for (int f = 0; f < 4; f++) { ksum_loc[f][0] = 0.f; ksum_loc[f][1] = 0.f; }

#pragma unroll
    for (int mi = 0; mi < 4; mi++) {
        int mrow0 = mBase + wm * 64 + mi * 16 + g;
#pragma unroll
        for (int f = 0; f < 4; f++) {
            int j0 = jBase + wn * 32 + f * 8 + 2 * l4;
            int jm = isK ? (j0 - Cch) : j0;
            float b0 = bias[j0], b1 = bias[j0 + 1];
#pragma unroll
            for (int rr = 0; rr < 2; rr++) {
                int m = mrow0 + rr * 8;
                float re = (rr == 0 ? c[mi][f].x : c[mi][f].z) + b0;
                float im = (rr == 0 ? c[mi][f].y : c[mi][f].w) + b1;
                re = (re > 0.f) ? (re + 1.f) : __expf(re);
                im = (im > 0.f) ? (im + 1.f) : __expf(im);
                int n = m & (Ntok - 1);
                float2 cs = g_rope[(size_t)n * 192 + (jm >> 1)];
                float rre = cs.x * re - cs.y * im;
                float rim = cs.y * re + cs.x * im;
                size_t off = (size_t)m * Cch + jm;
                uint32_t pk = packbf(rre, rim);
                if (!isK) {
                    *(uint32_t*)&g_qrb[off] = pk;
                } else {
                    *(uint32_t*)&g_krb[off] = pk;
                    ksum_loc[f][0] += re;
                    ksum_loc[f][1] += im;
                }
            }
        }
    }

    if (isK) {
#pragma unroll
        for (int f = 0; f < 4; f++) {
#pragma unroll
            for (int e = 0; e < 2; e++) {
                float v = ksum_loc[f][e];
                v += __shfl_xor_sync(0xffffffffu, v, 4);
                v += __shfl_xor_sync(0xffffffffu, v, 8);
                v += __shfl_xor_sync(0xffffffffu, v, 16);
                if (g == 0) {
                    int jm = (jBase - Cch) + wn * 32 + f * 8 + 2 * l4 + e;
                    atomicAdd(&g_ksum[bb * Cch + jm], v);
                }
            }
        }
    }
}

// ---------------------------------------------------------------------------
// kv[b][h] += (1/N) sum_n outer(k_rope, v);  bf16 inputs, fp32 accumulate.
// ---------------------------------------------------------------------------
#define KVCH 32
#define KVSPLIT 32
#define KVROW 256
#define KVTILE (KVCH * KVROW)

__global__ __launch_bounds__(256) void kv_kernel()
{
    int b = blockIdx.x, hq = blockIdx.y, s = blockIdx.z;
    int tid = threadIdx.x;
    __shared__ __align__(16) uint8_t ksm[2 * KVTILE];
    __shared__ __align__(16) uint8_t vsm[2 * KVTILE];

    int sub = tid >> 6;
    int st  = tid & 63;
    int d0  = (st >> 3) * 4;
    int e0  = (st & 7) * 4;

    float a[4][4];
#pragma unroll
    for (int r = 0; r < 4; r++)
#pragma unroll
        for (int cc = 0; cc < 4; cc++) a[r][cc] = 0.f;

    const int CHUNK = Ntok / KVSPLIT;
    const int NSTG  = CHUNK / KVCH;
    int nBase = s * CHUNK;
    const __nv_bfloat16* kr = g_krb + ((size_t)b * Ntok + nBase) * Cch + hq * 128;
    const __nv_bfloat16* vv = g_xbf + ((size_t)b * Ntok + nBase) * Cch + hq * 128;

    int ln[2], lc[2];
#pragma unroll
    for (int i = 0; i < 2; i++) { int idx = tid + i * 256; ln[i] = idx >> 4; lc[i] = (idx & 15) * 8; }
    uint32_t ksB = (uint32_t)__cvta_generic_to_shared(ksm);
    uint32_t vsB = (uint32_t)__cvta_generic_to_shared(vsm);

    auto load_stage = [&](int stg, int buf) {
#pragma unroll
        for (int i = 0; i < 2; i++) {
            uint32_t so = (uint32_t)(buf * KVTILE + ln[i] * KVROW + lc[i] * 2);
            size_t go = (size_t)(stg * KVCH + ln[i]) * Cch + lc[i];
            cp16(ksB + so, kr + go);
            cp16(vsB + so, vv + go);
        }
        asm volatile("cp.async.commit_group;");
    };

    load_stage(0, 0);
    for (int stg = 0; stg < NSTG; stg++) {
        if (stg + 1 < NSTG) {
            load_stage(stg + 1, (stg + 1) & 1);
            asm volatile("cp.async.wait_group 1;");
        } else {
            asm volatile("cp.async.wait_group 0;");
        }
        __syncthreads();
        int buf = stg & 1;
        const uint8_t* kb = ksm + buf * KVTILE + (sub * 32 + d0) * 2;
        const uint8_t* vb = vsm + buf * KVTILE + (sub * 32 + e0) * 2;
#pragma unroll
        for (int n = 0; n < KVCH; n++) {
            const __nv_bfloat162* kp = (const __nv_bfloat162*)(kb + n * KVROW);
            const __nv_bfloat162* vp = (const __nv_bfloat162*)(vb + n * KVROW);
            float2 k01 = __bfloat1622float2(kp[0]);
            float2 k23 = __bfloat1622float2(kp[1]);
            float2 v01 = __bfloat1622float2(vp[0]);
            float2 v23 = __bfloat1622float2(vp[1]);
            float kk[4] = {k01.x, k01.y, k23.x, k23.y};
            float vr[4] = {v01.x, v01.y, v23.x, v23.y};
#pragma unroll
            for (int r = 0; r < 4; r++)
#pragma unroll
                for (int cc = 0; cc < 4; cc++) a[r][cc] += kk[r] * vr[cc];
        }
        __syncthreads();
    }

    const float inv = 1.0f / (float)Ntok;
    float* dst = g_kv + (size_t)(b * NH + hq * 4 + sub) * DH * DH;
#pragma unroll
    for (int r = 0; r < 4; r++)
#pragma unroll
        for (int cc = 0; cc < 4; cc++)
            atomicAdd(&dst[(d0 + r) * DH + e0 + cc], a[r][cc] * inv);
}

// ---------------------------------------------------------------------------
// Finalize v2: tensor-core attention epilogue + depthwise conv.
// Block = (hh, half, b): 32 tokens, 384 threads (warp = head).
// Phase 1: cp.async q_rope rows -> smem; kv -> bf16 B-frag smem; z via shfl.
// Phase 2: 16x mma.m16n8k16 per warp (64tok... 32tok x 32e x k32).
// Phase 3: scale by z -> fp32 smem O (stride 388: conflict-free).
// Phase 4: channel-major rolling 3x3 conv + add O -> out.
// ---------------------------------------------------------------------------
#define FQ_BYTES 784            // Q row stride (392 bf16)
#define FQ_SIZE  (32 * FQ_BYTES)            // 25088
#define FB_OFF   FQ_SIZE
#define FB_SIZE  (NH * DH * 80)             // 30720
#define FO_OFF   (FB_OFF + FB_SIZE)         // 55808
#define FO_STRIDE 388
#define FO_SIZE  (32 * FO_STRIDE * 4)       // 49664
#define FZ_OFF   (FO_OFF + FO_SIZE)         // 105472
#define FIN_SMEM (FZ_OFF + NH * 32 * 4)     // 107008

__global__ __launch_bounds__(384) void finalize_kernel(
    const float* __restrict__ x, const float* __restrict__ lepe_w,
    const float* __restrict__ lepe_b, float* __restrict__ out)
{
    extern __shared__ __align__(16) uint8_t fsm[];
    __nv_bfloat16* Q = (__nv_bfloat16*)fsm;
    uint8_t* Bkv = fsm + FB_OFF;
    float* O  = (float*)(fsm + FO_OFF);
    float* zs = (float*)(fsm + FZ_OFF);

    int hh = blockIdx.x, half = blockIdx.y, b = blockIdx.z;
    int t = threadIdx.x;
    int h = t >> 5, lane = t & 31;
    bool even = ((lane & 1) == 0);
    int n0 = hh * HRES + half * 32;          // first global token of block

    uint32_t qB = (uint32_t)__cvta_generic_to_shared(Q);

    // Phase 1a: stage q_rope (32 rows x 384 bf16) via cp.async
    {
        const __nv_bfloat16* qsrc = g_qrb + ((size_t)b * Ntok + n0) * Cch;
#pragma unroll
        for (int i = 0; i < 4; i++) {
            int idx = i * 384 + t;
            int row = idx / 48, col = idx % 48;
            cp16(qB + (uint32_t)(row * FQ_BYTES + col * 16),
                 qsrc + (size_t)row * Cch + col * 8);
        }
        asm volatile("cp.async.commit_group;");
    }

    // Phase 1b: k_mean for this channel
    float km  = g_ksum[b * Cch + t] * (1.0f / (float)Ntok);
    float kmp = __shfl_xor_sync(0xffffffffu, km, 1);

    // Phase 1c: kv[b,h] -> bf16 transposed B tile (B[e][d] = kv[d][e])
    {
        const float* kvh = g_kv + (size_t)(b * NH + h) * DH * DH;
        __nv_bfloat16* Bh = (__nv_bfloat16*)(Bkv + h * (DH * 80));
#pragma unroll
        for (int d = 0; d < DH; d++) {
            float v = kvh[d * DH + lane];
            Bh[lane * 40 + d] = __float2bfloat16(v);
        }
    }

    asm volatile("cp.async.wait_group 0;");
    __syncthreads();

    // Phase 1d: z[w] = 1 / (q_rope . R_n(k_mean) + eps), per head
#pragma unroll 4
    for (int w = 0; w < 32; w++) {
        float2 cs = g_rope[(size_t)(n0 + w) * 192 + (h * 16 + (lane >> 1))];
        float qv = __bfloat162float(Q[w * 392 + h * 32 + lane]);
        float rkm = even ? (cs.x * km - cs.y * kmp) : (cs.y * kmp + cs.x * km);
        float prod = qv * rkm;
#pragma unroll
        for (int o = 16; o > 0; o >>= 1)
            prod += __shfl_xor_sync(0xffffffffu, prod, o);
        if (lane == 0) zs[h * 32 + w] = 1.0f / (prod + 1e-6f);
    }
    __syncwarp();

    // Phase 2: MMA — out32x32 = Q[32 tok x 32 d] @ kv[32 d x 32 e]
    float4 c[2][4];
#pragma unroll
    for (int i = 0; i < 2; i++)
#pragma unroll
        for (int f = 0; f < 4; f++) c[i][f] = make_float4(0.f, 0.f, 0.f, 0.f);
    {
        int qq = lane >> 3, r8 = lane & 7;
        uint32_t aOff = (uint32_t)(((qq & 1) * 8 + r8) * FQ_BYTES + (qq >> 1) * 16);
        uint32_t bOff = (uint32_t)(((qq >> 1) * 8 + r8) * 80 + (qq & 1) * 16);
        uint32_t bB = (uint32_t)__cvta_generic_to_shared(Bkv) + (uint32_t)(h * DH * 80);
#pragma unroll
        for (int kk = 0; kk < 32; kk += 16) {
            uint32_t a[2][4], bb[2][4];
#pragma unroll
            for (int tf = 0; tf < 2; tf++)
                ldm_x4(a[tf], qB + (uint32_t)(tf * 16 * FQ_BYTES + (h * 32 + kk) * 2) + aOff);
#pragma unroll
            for (int bg = 0; bg < 2; bg++)
                ldm_x4(bb[bg], bB + (uint32_t)(bg * 16 * 80 + kk * 2) + bOff);
#pragma unroll
            for (int tf = 0; tf < 2; tf++)
#pragma unroll
                for (int bg = 0; bg < 2; bg++) {
                    mma16(c[tf][bg * 2],     a[tf], bb[bg][0], bb[bg][1]);
                    mma16(c[tf][bg * 2 + 1], a[tf], bb[bg][2], bb[bg][3]);
                }
        }
    }
    __syncwarp();

    // Phase 3: scale by z, store fp32 to O
    {
        int g = lane >> 2, l4 = lane & 3;
#pragma unroll
        for (int tf = 0; tf < 2; tf++) {
            float zlo = zs[h * 32 + tf * 16 + g];
            float zhi = zs[h * 32 + tf * 16 + g + 8];
#pragma unroll
            for (int f = 0; f < 4; f++) {
                int e = h * 32 + f * 8 + 2 * l4;
                float* lo = &O[(tf * 16 + g) * FO_STRIDE + e];
                float* hi = &O[(tf * 16 + g + 8) * FO_STRIDE + e];
                lo[0] = c[tf][f].x * zlo;  lo[1] = c[tf][f].y * zlo;
                hi[0] = c[tf][f].z * zhi;  hi[1] = c[tf][f].w * zhi;
            }
        }
    }
    __syncthreads();

    // Phase 4: depthwise 3x3 conv (channel-major, rolling window) + add O
    float wl[9];
#pragma unroll
    for (int i = 0; i < 9; i++) wl[i] = lepe_w[t * 9 + i];
    float lb = lepe_b[t];

    const size_t rowStride = (size_t)HRES * Cch;
    const float* xb = x + (size_t)b * Ntok * Cch + t;
    int wb = half * 32;
    bool rok[3];
    const float* xr[3];
#pragma unroll
    for (int r = 0; r < 3; r++) {
        int yy = hh - 1 + r;
        rok[r] = (yy >= 0 && yy < HRES);
        xr[r] = xb + (size_t)(rok[r] ? yy : 0) * rowStride;
    }
    float cprev[3], ccur[3], cnext[3];
#pragma unroll
    for (int r = 0; r < 3; r++) {
        cprev[r] = (rok[r] && wb > 0) ? xr[r][(size_t)(wb - 1) * Cch] : 0.f;
        ccur[r]  = rok[r] ? xr[r][(size_t)wb * Cch] : 0.f;
        cnext[r] = rok[r] ? xr[r][(size_t)(wb + 1) * Cch] : 0.f;
    }

    float* orow = out + ((size_t)b * Ntok + n0) * Cch + t;

    for (int w = 0; w < 32; w++) {
        float lp = lb;
#pragma unroll
        for (int r = 0; r < 3; r++)
            lp += cprev[r] * wl[r * 3 + 0] + ccur[r] * wl[r * 3 + 1]
                + cnext[r] * wl[r * 3 + 2];

        orow[(size_t)w * Cch] = lp + O[w * FO_STRIDE + t];

#pragma unroll
        for (int r = 0; r < 3; r++) { cprev[r] = ccur[r]; ccur[r] = cnext[r]; }
        int xx = wb + w + 2;
        bool cok = (xx < HRES);
#pragma unroll
        for (int r = 0; r < 3; r++)
            cnext[r] = (rok[r] && cok) ? xr[r][(size_t)xx * Cch] : 0.f;
    }
}

// ---------------------------------------------------------------------------
extern "C" void kernel_launch(void* const* d_in, const int* in_sizes, int n_in,
                              void* d_out, int out_size)
{
    const float* x      = (const float*)d_in[0];
    const float* qk_w   = (const float*)d_in[1];
    const float* qk_b   = (const float*)d_in[2];
    const float* lepe_w = (const float*)d_in[3];
    const float* lepe_b = (const float*)d_in[4];
    float* out = (float*)d_out;

    cudaFuncSetAttribute(gemm_rope_tc, cudaFuncAttributeMaxDynamicSharedMemorySize, GEMM_SMEM);
    cudaFuncSetAttribute(finalize_kernel, cudaFuncAttributeMaxDynamicSharedMemorySize, FIN_SMEM);

    rope_table_kernel<<<Ntok, 192>>>();
    int zn = Bsz * NH * DH * DH;
    zero_scratch_kernel<<<(zn + 255) / 256, 256>>>();
    int wblk = ((TWOC * Cch) / 8 + 255) / 256;
    convert_kernel<<<XBLK + wblk, 256>>>(x, qk_w);
    gemm_rope_tc<<<dim3(TWOC / BN, (Bsz * Ntok) / BM), 256, GEMM_SMEM>>>(qk_b);
    kv_kernel<<<dim3(Bsz, NH / 4, KVSPLIT), 256>>>();
    finalize_kernel<<<dim3(HRES, 2, Bsz), 384, FIN_SMEM>>>(x, lepe_w, lepe_b, out);
}

// round 9
// speedup vs baseline: 3.7092x; 1.0570x over previous
#include <cuda_runtime.h>
#include <cuda_bf16.h>
#include <cstdint>

#define Bsz 16
#define Ntok 4096
#define Cch 384
#define HRES 64
#define NH 12
#define DH 32
#define TWOC 768

// Scratch (device globals: allocation-free rule)
__device__ __nv_bfloat16 g_xbf[Bsz * Ntok * Cch];   // bf16 copy of x
__device__ __nv_bfloat16 g_wbf[TWOC * Cch];         // bf16 copy of qk_w
__device__ __nv_bfloat16 g_qrb[Bsz * Ntok * Cch];   // roped q (bf16)
__device__ __nv_bfloat16 g_krb[Bsz * Ntok * Cch];   // roped k (bf16)
__device__ float  g_ksum[Bsz * Cch];                // sum_n k (unroped, fp32)
__device__ float  g_kv  [Bsz * NH * DH * DH];
__device__ float2 g_rope[Ntok * (Cch / 2)];

// ---------------------------------------------------------------------------
__device__ __forceinline__ uint32_t packbf(float a, float b) {
    __nv_bfloat162 h = __float22bfloat162_rn(make_float2(a, b));
    return *reinterpret_cast<uint32_t*>(&h);
}

__device__ __forceinline__ void ldm_x4(uint32_t* d, uint32_t addr) {
    asm volatile("ldmatrix.sync.aligned.m8n8.x4.shared.b16 {%0,%1,%2,%3}, [%4];"
                 : "=r"(d[0]), "=r"(d[1]), "=r"(d[2]), "=r"(d[3]) : "r"(addr));
}

__device__ __forceinline__ void mma16(float4& d, const uint32_t* a,
                                      uint32_t b0, uint32_t b1) {
    asm volatile(
        "mma.sync.aligned.m16n8k16.row.col.f32.bf16.bf16.f32 "
        "{%0,%1,%2,%3},{%4,%5,%6,%7},{%8,%9},{%0,%1,%2,%3};\n"
        : "+f"(d.x), "+f"(d.y), "+f"(d.z), "+f"(d.w)
        : "r"(a[0]), "r"(a[1]), "r"(a[2]), "r"(a[3]), "r"(b0), "r"(b1));
}

__device__ __forceinline__ void cp16(uint32_t smem, const void* g) {
    asm volatile("cp.async.cg.shared.global [%0], [%1], 16;" :: "r"(smem), "l"(g));
}

// ---------------------------------------------------------------------------
// Fused setup: rope table + zero scratch + bf16 conversion, one launch.
// blocks [0,3072): rope  [3072,3840): zero  [3840,16128): conv x  [16128,...): conv w
// ---------------------------------------------------------------------------
#define SB_ROPE 3072
#define SB_ZERO (SB_ROPE + 768)
#define SB_X    (SB_ZERO + 12288)
#define SB_W    (SB_X + 144)

__global__ __launch_bounds__(256) void setup_kernel(
    const float* __restrict__ x, const float* __restrict__ w)
{
    int blk = blockIdx.x;
    if (blk < SB_ROPE) {
        int i = blk * 256 + threadIdx.x;      // < 786432
        int n = i / 192, p = i % 192;
        int hh = n >> 6, ww = n & 63;
        int j = (p < 96) ? p : (p - 96);
        float theta = __expf(-((float)j * (1.0f / 96.0f)) * 9.210340371976184f);
        float pos = (p < 96) ? (float)hh : (float)ww;
        float s, c;
        sincosf(pos * theta, &s, &c);
        g_rope[(size_t)n * 192 + p] = make_float2(c, s);
    } else if (blk < SB_ZERO) {
        int i = (blk - SB_ROPE) * 256 + threadIdx.x;   // < 196608
        if (i < Bsz * Cch) g_ksum[i] = 0.f;
        g_kv[i] = 0.f;
    } else if (blk < SB_X) {
        size_t o = ((size_t)(blk - SB_ZERO) * 256 + threadIdx.x) * 8;
        float4 a = *(const float4*)(x + o);
        float4 b = *(const float4*)(x + o + 4);
        uint4 u = make_uint4(packbf(a.x, a.y), packbf(a.z, a.w),
                             packbf(b.x, b.y), packbf(b.z, b.w));
        *(uint4*)&g_xbf[o] = u;
    } else {
        size_t o = ((size_t)(blk - SB_X) * 256 + threadIdx.x) * 8;
        if (o < (size_t)TWOC * Cch) {
            float4 a = *(const float4*)(w + o);
            float4 b = *(const float4*)(w + o + 4);
            uint4 u = make_uint4(packbf(a.x, a.y), packbf(a.z, a.w),
                                 packbf(b.x, b.y), packbf(b.z, b.w));
            *(uint4*)&g_wbf[o] = u;
        }
    }
}

// ---------------------------------------------------------------------------
// GEMM qk = x @ W^T + b via bf16 MMA, cp.async 3-stage pipeline.
// BM=128 BN=128 BK=32, 256 threads (8 warps: 2 in M x 4 in N), warp 64x32.
// grid (6 j-blocks fast, 512 m-blocks).
// ---------------------------------------------------------------------------
#define BM 128
#define BN 128
#define BK 32
#define STAGES 3
#define NKT (Cch / BK)          // 12
#define AROW 80                  // bytes per smem row (40 bf16)
#define ATILE (BM * AROW)        // 10240
#define WTILE (BN * AROW)        // 10240
#define GEMM_SMEM (STAGES * (ATILE + WTILE))   // 61440

__global__ __launch_bounds__(256, 2) void gemm_rope_tc(const float* __restrict__ bias)
{
    extern __shared__ __align__(16) uint8_t gsm[];
    uint8_t* smA = gsm;
    uint8_t* smW = gsm + STAGES * ATILE;

    int tid  = threadIdx.x;
    int warp = tid >> 5, lane = tid & 31;
    int wm = warp >> 2, wn = warp & 3;
    int g  = lane >> 2, l4 = lane & 3;
    int r8 = lane & 7,  qq = lane >> 3;

    int jBase = blockIdx.x * BN;
    int mBase = blockIdx.y * BM;

    const __nv_bfloat16* xblk = g_xbf + (size_t)mBase * Cch;
    const __nv_bfloat16* wblk = g_wbf + (size_t)jBase * Cch;

    int am[2], ak[2];
#pragma unroll
    for (int i = 0; i < 2; i++) { int idx = tid + i * 256; am[i] = idx >> 2; ak[i] = (idx & 3) * 8; }

    uint32_t aBase = (uint32_t)__cvta_generic_to_shared(smA);
    uint32_t wBase = (uint32_t)__cvta_generic_to_shared(smW);
    uint32_t aOff = (uint32_t)(((qq & 1) * 8 + r8) * AROW + (qq >> 1) * 16);
    uint32_t bOff = (uint32_t)(((qq >> 1) * 8 + r8) * AROW + (qq & 1) * 16);

    auto loadTile = [&](int t, int buf) {
        int k0 = t * BK;
#pragma unroll
        for (int i = 0; i < 2; i++) {
            cp16(aBase + (uint32_t)(buf * ATILE + am[i] * AROW + ak[i] * 2),
                 xblk + (size_t)am[i] * Cch + k0 + ak[i]);
            cp16(wBase + (uint32_t)(buf * WTILE + am[i] * AROW + ak[i] * 2),
                 wblk + (size_t)am[i] * Cch + k0 + ak[i]);
        }
        asm volatile("cp.async.commit_group;");
    };

    float4 c[4][4];
#pragma unroll
    for (int i = 0; i < 4; i++)
#pragma unroll
        for (int f = 0; f < 4; f++) c[i][f] = make_float4(0.f, 0.f, 0.f, 0.f);

    loadTile(0, 0);
    loadTile(1, 1);

    for (int t = 0; t < NKT; t++) {
        asm volatile("cp.async.wait_group 1;");
        __syncthreads();
        if (t + 2 < NKT) loadTile(t + 2, (t + 2) % STAGES);

        int buf = t % STAGES;
        uint32_t aT = aBase + (uint32_t)(buf * ATILE);
        uint32_t wT = wBase + (uint32_t)(buf * WTILE);
#pragma unroll
        for (int kk = 0; kk < BK; kk += 16) {
            uint32_t a[4][4], b[2][4];
#pragma unroll
            for (int mi = 0; mi < 4; mi++)
                ldm_x4(a[mi], aT + (uint32_t)((wm * 64 + mi * 16) * AROW + kk * 2) + aOff);
#pragma unroll
            for (int bg = 0; bg < 2; bg++)
                ldm_x4(b[bg], wT + (uint32_t)((wn * 32 + bg * 16) * AROW + kk * 2) + bOff);
#pragma unroll
            for (int mi = 0; mi < 4; mi++)
#pragma unroll
                for (int bg = 0; bg < 2; bg++) {
                    mma16(c[mi][bg * 2],     a[mi], b[bg][0], b[bg][1]);
                    mma16(c[mi][bg * 2 + 1], a[mi], b[bg][2], b[bg][3]);
                }
        }
    }

    // ---- fused epilogue: bias, elu+1, RoPE, k-sum; bf16 outputs ----
    bool isK = (jBase >= Cch);
    int bb = mBase >> 12;
    float ksum_loc[4][2];
#pragma unroll
    for (int f = 0; f < 4; f++) { ksum_loc[f][0] = 0.f; ksum_loc[f][1] = 0.f; }

#pragma unroll
    for (int mi = 0; mi < 4; mi++) {
        int mrow0 = mBase + wm * 64 + mi * 16 + g;
#pragma unroll
        for (int f = 0; f < 4; f++) {
            int j0 = jBase + wn * 32 + f * 8 + 2 * l4;
            int jm = isK ? (j0 - Cch) : j0;
            float b0 = bias[j0], b1 = bias[j0 + 1];
#pragma unroll
            for (int rr = 0; rr < 2; rr++) {
                int m = mrow0 + rr * 8;
                float re = (rr == 0 ? c[mi][f].x : c[mi][f].z) + b0;
                float im = (rr == 0 ? c[mi][f].y : c[mi][f].w) + b1;
                re = (re > 0.f) ? (re + 1.f) : __expf(re);
                im = (im > 0.f) ? (im + 1.f) : __expf(im);
                int n = m & (Ntok - 1);
                float2 cs = g_rope[(size_t)n * 192 + (jm >> 1)];
                float rre = cs.x * re - cs.y * im;
                float rim = cs.y * re + cs.x * im;
                size_t off = (size_t)m * Cch + jm;
                uint32_t pk = packbf(rre, rim);
                if (!isK) {
                    *(uint32_t*)&g_qrb[off] = pk;
                } else {
                    *(uint32_t*)&g_krb[off] = pk;
                    ksum_loc[f][0] += re;
                    ksum_loc[f][1] += im;
                }
            }
        }
    }

    if (isK) {
#pragma unroll
        for (int f = 0; f < 4; f++) {
#pragma unroll
            for (int e = 0; e < 2; e++) {
                float v = ksum_loc[f][e];
                v += __shfl_xor_sync(0xffffffffu, v, 4);
                v += __shfl_xor_sync(0xffffffffu, v, 8);
                v += __shfl_xor_sync(0xffffffffu, v, 16);
                if (g == 0) {
                    int jm = (jBase - Cch) + wn * 32 + f * 8 + 2 * l4 + e;
                    atomicAdd(&g_ksum[bb * Cch + jm], v);
                }
            }
        }
    }
}

// ---------------------------------------------------------------------------
// kv[b][h] += (1/N) sum_n outer(k_rope, v);  bf16 inputs, fp32 accumulate.
// ---------------------------------------------------------------------------
#define KVCH 32
#define KVSPLIT 32
#define KVROW 256
#define KVTILE (KVCH * KVROW)

__global__ __launch_bounds__(256) void kv_kernel()
{
    int b = blockIdx.x, hq = blockIdx.y, s = blockIdx.z;
    int tid = threadIdx.x;
    __shared__ __align__(16) uint8_t ksm[2 * KVTILE];
    __shared__ __align__(16) uint8_t vsm[2 * KVTILE];

    int sub = tid >> 6;
    int st  = tid & 63;
    int d0  = (st >> 3) * 4;
    int e0  = (st & 7) * 4;

    float a[4][4];
#pragma unroll
    for (int r = 0; r < 4; r++)
#pragma unroll
        for (int cc = 0; cc < 4; cc++) a[r][cc] = 0.f;

    const int CHUNK = Ntok / KVSPLIT;
    const int NSTG  = CHUNK / KVCH;
    int nBase = s * CHUNK;
    const __nv_bfloat16* kr = g_krb + ((size_t)b * Ntok + nBase) * Cch + hq * 128;
    const __nv_bfloat16* vv = g_xbf + ((size_t)b * Ntok + nBase) * Cch + hq * 128;

    int ln[2], lc[2];
#pragma unroll
    for (int i = 0; i < 2; i++) { int idx = tid + i * 256; ln[i] = idx >> 4; lc[i] = (idx & 15) * 8; }
    uint32_t ksB = (uint32_t)__cvta_generic_to_shared(ksm);
    uint32_t vsB = (uint32_t)__cvta_generic_to_shared(vsm);

    auto load_stage = [&](int stg, int buf) {
#pragma unroll
        for (int i = 0; i < 2; i++) {
            uint32_t so = (uint32_t)(buf * KVTILE + ln[i] * KVROW + lc[i] * 2);
            size_t go = (size_t)(stg * KVCH + ln[i]) * Cch + lc[i];
            cp16(ksB + so, kr + go);
            cp16(vsB + so, vv + go);
        }
        asm volatile("cp.async.commit_group;");
    };

    load_stage(0, 0);
    for (int stg = 0; stg < NSTG; stg++) {
        if (stg + 1 < NSTG) {
            load_stage(stg + 1, (stg + 1) & 1);
            asm volatile("cp.async.wait_group 1;");
        } else {
            asm volatile("cp.async.wait_group 0;");
        }
        __syncthreads();
        int buf = stg & 1;
        const uint8_t* kb = ksm + buf * KVTILE + (sub * 32 + d0) * 2;
        const uint8_t* vb = vsm + buf * KVTILE + (sub * 32 + e0) * 2;
#pragma unroll
        for (int n = 0; n < KVCH; n++) {
            const __nv_bfloat162* kp = (const __nv_bfloat162*)(kb + n * KVROW);
            const __nv_bfloat162* vp = (const __nv_bfloat162*)(vb + n * KVROW);
            float2 k01 = __bfloat1622float2(kp[0]);
            float2 k23 = __bfloat1622float2(kp[1]);
            float2 v01 = __bfloat1622float2(vp[0]);
            float2 v23 = __bfloat1622float2(vp[1]);
            float kk[4] = {k01.x, k01.y, k23.x, k23.y};
            float vr[4] = {v01.x, v01.y, v23.x, v23.y};
#pragma unroll
            for (int r = 0; r < 4; r++)
#pragma unroll
                for (int cc = 0; cc < 4; cc++) a[r][cc] += kk[r] * vr[cc];
        }
        __syncthreads();
    }

    const float inv = 1.0f / (float)Ntok;
    float* dst = g_kv + (size_t)(b * NH + hq * 4 + sub) * DH * DH;
#pragma unroll
    for (int r = 0; r < 4; r++)
#pragma unroll
        for (int cc = 0; cc < 4; cc++)
            atomicAdd(&dst[(d0 + r) * DH + e0 + cc], a[r][cc] * inv);
}

// ---------------------------------------------------------------------------
// Finalize: tensor-core attention epilogue + chunked depthwise conv (fp32 x).
// Block = (hh, half, b): 32 tokens, 384 threads (warp = head).
// Phase 4 processes 8 columns per chunk: 30 halo loads issued back-to-back
// (MLP 30/thread), then pure FFMA. Conv reads fp32 x for accuracy.
// ---------------------------------------------------------------------------
#define FQ_BYTES 784
#define FQ_SIZE  (32 * FQ_BYTES)
#define FB_OFF   FQ_SIZE
#define FB_SIZE  (NH * DH * 80)
#define FO_OFF   (FB_OFF + FB_SIZE)
#define FO_STRIDE 388
#define FO_SIZE  (32 * FO_STRIDE * 4)
#define FZ_OFF   (FO_OFF + FO_SIZE)
#define FIN_SMEM (FZ_OFF + NH * 32 * 4)

__global__ __launch_bounds__(384) void finalize_kernel(
    const float* __restrict__ x, const float* __restrict__ lepe_w,
    const float* __restrict__ lepe_b, float* __restrict__ out)
{
    extern __shared__ __align__(16) uint8_t fsm[];
    __nv_bfloat16* Q = (__nv_bfloat16*)fsm;
    uint8_t* Bkv = fsm + FB_OFF;
    float* O  = (float*)(fsm + FO_OFF);
    float* zs = (float*)(fsm + FZ_OFF);

    int hh = blockIdx.x, half = blockIdx.y, b = blockIdx.z;
    int t = threadIdx.x;
    int h = t >> 5, lane = t & 31;
    bool even = ((lane & 1) == 0);
    int n0 = hh * HRES + half * 32;

    uint32_t qB = (uint32_t)__cvta_generic_to_shared(Q);

    {
        const __nv_bfloat16* qsrc = g_qrb + ((size_t)b * Ntok + n0) * Cch;
#pragma unroll
        for (int i = 0; i < 4; i++) {
            int idx = i * 384 + t;
            int row = idx / 48, col = idx % 48;
            cp16(qB + (uint32_t)(row * FQ_BYTES + col * 16),
                 qsrc + (size_t)row * Cch + col * 8);
        }
        asm volatile("cp.async.commit_group;");
    }

    float km  = g_ksum[b * Cch + t] * (1.0f / (float)Ntok);
    float kmp = __shfl_xor_sync(0xffffffffu, km, 1);

    {
        const float* kvh = g_kv + (size_t)(b * NH + h) * DH * DH;
        __nv_bfloat16* Bh = (__nv_bfloat16*)(Bkv + h * (DH * 80));
#pragma unroll
        for (int d = 0; d < DH; d++) {
            float v = kvh[d * DH + lane];
            Bh[lane * 40 + d] = __float2bfloat16(v);
        }
    }

    asm volatile("cp.async.wait_group 0;");
    __syncthreads();

#pragma unroll 4
    for (int w = 0; w < 32; w++) {
        float2 cs = g_rope[(size_t)(n0 + w) * 192 + (h * 16 + (lane >> 1))];
        float qv = __bfloat162float(Q[w * 392 + h * 32 + lane]);
        float rkm = even ? (cs.x * km - cs.y * kmp) : (cs.y * kmp + cs.x * km);
        float prod = qv * rkm;
#pragma unroll
        for (int o = 16; o > 0; o >>= 1)
            prod += __shfl_xor_sync(0xffffffffu, prod, o);
        if (lane == 0) zs[h * 32 + w] = 1.0f / (prod + 1e-6f);
    }
    __syncwarp();

    float4 c[2][4];
#pragma unroll
    for (int i = 0; i < 2; i++)
#pragma unroll
        for (int f = 0; f < 4; f++) c[i][f] = make_float4(0.f, 0.f, 0.f, 0.f);
    {
        int qq = lane >> 3, r8 = lane & 7;
        uint32_t aOff = (uint32_t)(((qq & 1) * 8 + r8) * FQ_BYTES + (qq >> 1) * 16);
        uint32_t bOff = (uint32_t)(((qq >> 1) * 8 + r8) * 80 + (qq & 1) * 16);
        uint32_t bB = (uint32_t)__cvta_generic_to_shared(Bkv) + (uint32_t)(h * DH * 80);
#pragma unroll
        for (int kk = 0; kk < 32; kk += 16) {
            uint32_t a[2][4], bb[2][4];
#pragma unroll
            for (int tf = 0; tf < 2; tf++)
                ldm_x4(a[tf], qB + (uint32_t)(tf * 16 * FQ_BYTES + (h * 32 + kk) * 2) + aOff);
#pragma unroll
            for (int bg = 0; bg < 2; bg++)
                ldm_x4(bb[bg], bB + (uint32_t)(bg * 16 * 80 + kk * 2) + bOff);
#pragma unroll
            for (int tf = 0; tf < 2; tf++)
#pragma unroll
                for (int bg = 0; bg < 2; bg++) {
                    mma16(c[tf][bg * 2],     a[tf], bb[bg][0], bb[bg][1]);
                    mma16(c[tf][bg * 2 + 1], a[tf], bb[bg][2], bb[bg][3]);
                }
        }
    }
    __syncwarp();

    {
        int g = lane >> 2, l4 = lane & 3;
#pragma unroll
        for (int tf = 0; tf < 2; tf++) {
            float zlo = zs[h * 32 + tf * 16 + g];
            float zhi = zs[h * 32 + tf * 16 + g + 8];
#pragma unroll
            for (int f = 0; f < 4; f++) {
                int e = h * 32 + f * 8 + 2 * l4;
                float* lo = &O[(tf * 16 + g) * FO_STRIDE + e];
                float* hi = &O[(tf * 16 + g + 8) * FO_STRIDE + e];
                lo[0] = c[tf][f].x * zlo;  lo[1] = c[tf][f].y * zlo;
                hi[0] = c[tf][f].z * zhi;  hi[1] = c[tf][f].w * zhi;
            }
        }
    }
    __syncthreads();

    // Phase 4: chunked depthwise 3x3 conv (fp32 x) + add O
    float wl[9];
#pragma unroll
    for (int i = 0; i < 9; i++) wl[i] = lepe_w[t * 9 + i];
    float lb = lepe_b[t];

    const size_t rowStride = (size_t)HRES * Cch;
    const float* xb = x + (size_t)b * Ntok * Cch + t;
    int wb = half * 32;
    bool rok[3];
    const float* xr[3];
#pragma unroll
    for (int r = 0; r < 3; r++) {
        int yy = hh - 1 + r;
        rok[r] = (yy >= 0 && yy < HRES);
        xr[r] = xb + (size_t)(rok[r] ? yy : 0) * rowStride;
    }

    float* orow = out + ((size_t)b * Ntok + n0) * Cch + t;

#pragma unroll
    for (int ch = 0; ch < 4; ch++) {
        int base = wb + ch * 8;
        float v[3][10];
#pragma unroll
        for (int r = 0; r < 3; r++)
#pragma unroll
            for (int j = 0; j < 10; j++) {
                int col = base - 1 + j;
                bool ok = rok[r] && col >= 0 && col < HRES;
                v[r][j] = ok ? xr[r][(size_t)col * Cch] : 0.f;
            }
#pragma unroll
        for (int w = 0; w < 8; w++) {
            float lp = lb;
#pragma unroll
            for (int r = 0; r < 3; r++)
                lp += v[r][w] * wl[r * 3 + 0] + v[r][w + 1] * wl[r * 3 + 1]
                    + v[r][w + 2] * wl[r * 3 + 2];
            int wcol = ch * 8 + w;
            orow[(size_t)wcol * Cch] = lp + O[wcol * FO_STRIDE + t];
        }
    }
}

// ---------------------------------------------------------------------------
extern "C" void kernel_launch(void* const* d_in, const int* in_sizes, int n_in,
                              void* d_out, int out_size)
{
    const float* x      = (const float*)d_in[0];
    const float* qk_w   = (const float*)d_in[1];
    const float* qk_b   = (const float*)d_in[2];
    const float* lepe_w = (const float*)d_in[3];
    const float* lepe_b = (const float*)d_in[4];
    float* out = (float*)d_out;

    cudaFuncSetAttribute(gemm_rope_tc, cudaFuncAttributeMaxDynamicSharedMemorySize, GEMM_SMEM);
    cudaFuncSetAttribute(finalize_kernel, cudaFuncAttributeMaxDynamicSharedMemorySize, FIN_SMEM);

    setup_kernel<<<SB_W, 256>>>(x, qk_w);
    gemm_rope_tc<<<dim3(TWOC / BN, (Bsz * Ntok) / BM), 256, GEMM_SMEM>>>(qk_b);
    kv_kernel<<<dim3(Bsz, NH / 4, KVSPLIT), 256>>>();
    finalize_kernel<<<dim3(HRES, 2, Bsz), 384, FIN_SMEM>>>(x, lepe_w, lepe_b, out);
}

// round 10
// speedup vs baseline: 3.8434x; 1.0362x over previous
#include <cuda_runtime.h>
#include <cuda_bf16.h>
#include <cstdint>

#define Bsz 16
#define Ntok 4096
#define Cch 384
#define HRES 64
#define NH 12
#define DH 32
#define TWOC 768

// Scratch (device globals: allocation-free rule)
__device__ __nv_bfloat16 g_xbf[Bsz * Ntok * Cch];   // bf16 copy of x
__device__ __nv_bfloat16 g_wbf[TWOC * Cch];         // bf16 copy of qk_w
__device__ __nv_bfloat16 g_qrb[Bsz * Ntok * Cch];   // roped q (bf16)
__device__ __nv_bfloat16 g_krb[Bsz * Ntok * Cch];   // roped k (bf16)
__device__ float  g_ksum[Bsz * Cch];                // sum_n k (unroped, fp32)
__device__ float  g_kv  [Bsz * NH * DH * DH];
__device__ float2 g_rope[Ntok * (Cch / 2)];

// ---------------------------------------------------------------------------
__device__ __forceinline__ uint32_t packbf(float a, float b) {
    __nv_bfloat162 h = __float22bfloat162_rn(make_float2(a, b));
    return *reinterpret_cast<uint32_t*>(&h);
}

__device__ __forceinline__ void ldm_x4(uint32_t* d, uint32_t addr) {
    asm volatile("ldmatrix.sync.aligned.m8n8.x4.shared.b16 {%0,%1,%2,%3}, [%4];"
                 : "=r"(d[0]), "=r"(d[1]), "=r"(d[2]), "=r"(d[3]) : "r"(addr));
}

__device__ __forceinline__ void mma16(float4& d, const uint32_t* a,
                                      uint32_t b0, uint32_t b1) {
    asm volatile(
        "mma.sync.aligned.m16n8k16.row.col.f32.bf16.bf16.f32 "
        "{%0,%1,%2,%3},{%4,%5,%6,%7},{%8,%9},{%0,%1,%2,%3};\n"
        : "+f"(d.x), "+f"(d.y), "+f"(d.z), "+f"(d.w)
        : "r"(a[0]), "r"(a[1]), "r"(a[2]), "r"(a[3]), "r"(b0), "r"(b1));
}

__device__ __forceinline__ void cp16(uint32_t smem, const void* g) {
    asm volatile("cp.async.cg.shared.global [%0], [%1], 16;" :: "r"(smem), "l"(g));
}

// ---------------------------------------------------------------------------
// Fused setup: rope table + zero scratch + bf16 conversion, one launch.
// ---------------------------------------------------------------------------
#define SB_ROPE 3072
#define SB_ZERO (SB_ROPE + 768)
#define SB_X    (SB_ZERO + 12288)
#define SB_W    (SB_X + 144)

__global__ __launch_bounds__(256) void setup_kernel(
    const float* __restrict__ x, const float* __restrict__ w)
{
    int blk = blockIdx.x;
    if (blk < SB_ROPE) {
        int i = blk * 256 + threadIdx.x;      // < 786432
        int n = i / 192, p = i % 192;
        int hh = n >> 6, ww = n & 63;
        int j = (p < 96) ? p : (p - 96);
        float theta = __expf(-((float)j * (1.0f / 96.0f)) * 9.210340371976184f);
        float pos = (p < 96) ? (float)hh : (float)ww;
        float s, c;
        sincosf(pos * theta, &s, &c);
        g_rope[(size_t)n * 192 + p] = make_float2(c, s);
    } else if (blk < SB_ZERO) {
        int i = (blk - SB_ROPE) * 256 + threadIdx.x;   // < 196608
        if (i < Bsz * Cch) g_ksum[i] = 0.f;
        g_kv[i] = 0.f;
    } else if (blk < SB_X) {
        size_t o = ((size_t)(blk - SB_ZERO) * 256 + threadIdx.x) * 8;
        float4 a = *(const float4*)(x + o);
        float4 b = *(const float4*)(x + o + 4);
        uint4 u = make_uint4(packbf(a.x, a.y), packbf(a.z, a.w),
                             packbf(b.x, b.y), packbf(b.z, b.w));
        *(uint4*)&g_xbf[o] = u;
    } else {
        size_t o = ((size_t)(blk - SB_X) * 256 + threadIdx.x) * 8;
        if (o < (size_t)TWOC * Cch) {
            float4 a = *(const float4*)(w + o);
            float4 b = *(const float4*)(w + o + 4);
            uint4 u = make_uint4(packbf(a.x, a.y), packbf(a.z, a.w),
                                 packbf(b.x, b.y), packbf(b.z, b.w));
            *(uint4*)&g_wbf[o] = u;
        }
    }
}

// ---------------------------------------------------------------------------
// GEMM qk = x @ W^T + b via bf16 MMA, cp.async 3-stage pipeline.
// BM=128 BN=128 BK=32, 256 threads (8 warps: 2 in M x 4 in N), warp 64x32.
// ---------------------------------------------------------------------------
#define BM 128
#define BN 128
#define BK 32
#define STAGES 3
#define NKT (Cch / BK)          // 12
#define AROW 80                  // bytes per smem row (40 bf16)
#define ATILE (BM * AROW)        // 10240
#define WTILE (BN * AROW)        // 10240
#define GEMM_SMEM (STAGES * (ATILE + WTILE))   // 61440

__global__ __launch_bounds__(256, 2) void gemm_rope_tc(const float* __restrict__ bias)
{
    extern __shared__ __align__(16) uint8_t gsm[];
    uint8_t* smA = gsm;
    uint8_t* smW = gsm + STAGES * ATILE;

    int tid  = threadIdx.x;
    int warp = tid >> 5, lane = tid & 31;
    int wm = warp >> 2, wn = warp & 3;
    int g  = lane >> 2, l4 = lane & 3;
    int r8 = lane & 7,  qq = lane >> 3;

    int jBase = blockIdx.x * BN;
    int mBase = blockIdx.y * BM;

    const __nv_bfloat16* xblk = g_xbf + (size_t)mBase * Cch;
    const __nv_bfloat16* wblk = g_wbf + (size_t)jBase * Cch;

    int am[2], ak[2];
#pragma unroll
    for (int i = 0; i < 2; i++) { int idx = tid + i * 256; am[i] = idx >> 2; ak[i] = (idx & 3) * 8; }

    uint32_t aBase = (uint32_t)__cvta_generic_to_shared(smA);
    uint32_t wBase = (uint32_t)__cvta_generic_to_shared(smW);
    uint32_t aOff = (uint32_t)(((qq & 1) * 8 + r8) * AROW + (qq >> 1) * 16);
    uint32_t bOff = (uint32_t)(((qq >> 1) * 8 + r8) * AROW + (qq & 1) * 16);

    auto loadTile = [&](int t, int buf) {
        int k0 = t * BK;
#pragma unroll
        for (int i = 0; i < 2; i++) {
            cp16(aBase + (uint32_t)(buf * ATILE + am[i] * AROW + ak[i] * 2),
                 xblk + (size_t)am[i] * Cch + k0 + ak[i]);
            cp16(wBase + (uint32_t)(buf * WTILE + am[i] * AROW + ak[i] * 2),
                 wblk + (size_t)am[i] * Cch + k0 + ak[i]);
        }
        asm volatile("cp.async.commit_group;");
    };

    float4 c[4][4];
#pragma unroll
    for (int i = 0; i < 4; i++)
#pragma unroll
        for (int f = 0; f < 4; f++) c[i][f] = make_float4(0.f, 0.f, 0.f, 0.f);

    loadTile(0, 0);
    loadTile(1, 1);

    for (int t = 0; t < NKT; t++) {
        asm volatile("cp.async.wait_group 1;");
        __syncthreads();
        if (t + 2 < NKT) loadTile(t + 2, (t + 2) % STAGES);

        int buf = t % STAGES;
        uint32_t aT = aBase + (uint32_t)(buf * ATILE);
        uint32_t wT = wBase + (uint32_t)(buf * WTILE);
#pragma unroll
        for (int kk = 0; kk < BK; kk += 16) {
            uint32_t a[4][4], b[2][4];
#pragma unroll
            for (int mi = 0; mi < 4; mi++)
                ldm_x4(a[mi], aT + (uint32_t)((wm * 64 + mi * 16) * AROW + kk * 2) + aOff);
#pragma unroll
            for (int bg = 0; bg < 2; bg++)
                ldm_x4(b[bg], wT + (uint32_t)((wn * 32 + bg * 16) * AROW + kk * 2) + bOff);
#pragma unroll
            for (int mi = 0; mi < 4; mi++)
#pragma unroll
                for (int bg = 0; bg < 2; bg++) {
                    mma16(c[mi][bg * 2],     a[mi], b[bg][0], b[bg][1]);
                    mma16(c[mi][bg * 2 + 1], a[mi], b[bg][2], b[bg][3]);
                }
        }
    }

    // ---- fused epilogue: bias, elu+1, RoPE, k-sum; bf16 outputs ----
    bool isK = (jBase >= Cch);
    int bb = mBase >> 12;
    float ksum_loc[4][2];
#pragma unroll
    for (int f = 0; f < 4; f++) { ksum_loc[f][0] = 0.f; ksum_loc[f][1] = 0.f; }

#pragma unroll
    for (int mi = 0; mi < 4; mi++) {
        int mrow0 = mBase + wm * 64 + mi * 16 + g;
#pragma unroll
        for (int f = 0; f < 4; f++) {
            int j0 = jBase + wn * 32 + f * 8 + 2 * l4;
            int jm = isK ? (j0 - Cch) : j0;
            float b0 = bias[j0], b1 = bias[j0 + 1];
#pragma unroll
            for (int rr = 0; rr < 2; rr++) {
                int m = mrow0 + rr * 8;
                float re = (rr == 0 ? c[mi][f].x : c[mi][f].z) + b0;
                float im = (rr == 0 ? c[mi][f].y : c[mi][f].w) + b1;
                re = (re > 0.f) ? (re + 1.f) : __expf(re);
                im = (im > 0.f) ? (im + 1.f) : __expf(im);
                int n = m & (Ntok - 1);
                float2 cs = g_rope[(size_t)n * 192 + (jm >> 1)];
                float rre = cs.x * re - cs.y * im;
                float rim = cs.y * re + cs.x * im;
                size_t off = (size_t)m * Cch + jm;
                uint32_t pk = packbf(rre, rim);
                if (!isK) {
                    *(uint32_t*)&g_qrb[off] = pk;
                } else {
                    *(uint32_t*)&g_krb[off] = pk;
                    ksum_loc[f][0] += re;
                    ksum_loc[f][1] += im;
                }
            }
        }
    }

    if (isK) {
#pragma unroll
        for (int f = 0; f < 4; f++) {
#pragma unroll
            for (int e = 0; e < 2; e++) {
                float v = ksum_loc[f][e];
                v += __shfl_xor_sync(0xffffffffu, v, 4);
                v += __shfl_xor_sync(0xffffffffu, v, 8);
                v += __shfl_xor_sync(0xffffffffu, v, 16);
                if (g == 0) {
                    int jm = (jBase - Cch) + wn * 32 + f * 8 + 2 * l4 + e;
                    atomicAdd(&g_ksum[bb * Cch + jm], v);
                }
            }
        }
    }
}

// ---------------------------------------------------------------------------
// kv[b][h] += (1/N) sum_n outer(k_rope, v);  bf16 inputs, fp32 accumulate.
// ---------------------------------------------------------------------------
#define KVCH 32
#define KVSPLIT 32
#define KVROW 256
#define KVTILE (KVCH * KVROW)

__global__ __launch_bounds__(256) void kv_kernel()
{
    int b = blockIdx.x, hq = blockIdx.y, s = blockIdx.z;
    int tid = threadIdx.x;
    __shared__ __align__(16) uint8_t ksm[2 * KVTILE];
    __shared__ __align__(16) uint8_t vsm[2 * KVTILE];

    int sub = tid >> 6;
    int st  = tid & 63;
    int d0  = (st >> 3) * 4;
    int e0  = (st & 7) * 4;

    float a[4][4];
#pragma unroll
    for (int r = 0; r < 4; r++)
#pragma unroll
        for (int cc = 0; cc < 4; cc++) a[r][cc] = 0.f;

    const int CHUNK = Ntok / KVSPLIT;
    const int NSTG  = CHUNK / KVCH;
    int nBase = s * CHUNK;
    const __nv_bfloat16* kr = g_krb + ((size_t)b * Ntok + nBase) * Cch + hq * 128;
    const __nv_bfloat16* vv = g_xbf + ((size_t)b * Ntok + nBase) * Cch + hq * 128;

    int ln[2], lc[2];
#pragma unroll
    for (int i = 0; i < 2; i++) { int idx = tid + i * 256; ln[i] = idx >> 4; lc[i] = (idx & 15) * 8; }
    uint32_t ksB = (uint32_t)__cvta_generic_to_shared(ksm);
    uint32_t vsB = (uint32_t)__cvta_generic_to_shared(vsm);

    auto load_stage = [&](int stg, int buf) {
#pragma unroll
        for (int i = 0; i < 2; i++) {
            uint32_t so = (uint32_t)(buf * KVTILE + ln[i] * KVROW + lc[i] * 2);
            size_t go = (size_t)(stg * KVCH + ln[i]) * Cch + lc[i];
            cp16(ksB + so, kr + go);
            cp16(vsB + so, vv + go);
        }
        asm volatile("cp.async.commit_group;");
    };

    load_stage(0, 0);
    for (int stg = 0; stg < NSTG; stg++) {
        if (stg + 1 < NSTG) {
            load_stage(stg + 1, (stg + 1) & 1);
            asm volatile("cp.async.wait_group 1;");
        } else {
            asm volatile("cp.async.wait_group 0;");
        }
        __syncthreads();
        int buf = stg & 1;
        const uint8_t* kb = ksm + buf * KVTILE + (sub * 32 + d0) * 2;
        const uint8_t* vb = vsm + buf * KVTILE + (sub * 32 + e0) * 2;
#pragma unroll
        for (int n = 0; n < KVCH; n++) {
            const __nv_bfloat162* kp = (const __nv_bfloat162*)(kb + n * KVROW);
            const __nv_bfloat162* vp = (const __nv_bfloat162*)(vb + n * KVROW);
            float2 k01 = __bfloat1622float2(kp[0]);
            float2 k23 = __bfloat1622float2(kp[1]);
            float2 v01 = __bfloat1622float2(vp[0]);
            float2 v23 = __bfloat1622float2(vp[1]);
            float kk[4] = {k01.x, k01.y, k23.x, k23.y};
            float vr[4] = {v01.x, v01.y, v23.x, v23.y};
#pragma unroll
            for (int r = 0; r < 4; r++)
#pragma unroll
                for (int cc = 0; cc < 4; cc++) a[r][cc] += kk[r] * vr[cc];
        }
        __syncthreads();
    }

    const float inv = 1.0f / (float)Ntok;
    float* dst = g_kv + (size_t)(b * NH + hq * 4 + sub) * DH * DH;
#pragma unroll
    for (int r = 0; r < 4; r++)
#pragma unroll
        for (int cc = 0; cc < 4; cc++)
            atomicAdd(&dst[(d0 + r) * DH + e0 + cc], a[r][cc] * inv);
}

// ---------------------------------------------------------------------------
// Finalize: tensor-core attention epilogue + chunked depthwise conv (fp32 x).
// SMEM UNION: Q+Bkv live during phases 1-2; O overwrites them after the MMA
// (results in registers; __syncthreads at the boundary). 107KB -> 57KB smem
// => 2 blocks/SM.
// ---------------------------------------------------------------------------
#define FQ_BYTES 784
#define FQ_SIZE  (32 * FQ_BYTES)            // 25088
#define FB_OFF   FQ_SIZE
#define FB_SIZE  (NH * DH * 80)             // 30720
#define FO_STRIDE 388
#define FO_SIZE  (32 * FO_STRIDE * 4)       // 49664  (< FQ_SIZE + FB_SIZE)
#define FZ_OFF   (FQ_SIZE + FB_SIZE)        // 55808
#define FIN_SMEM (FZ_OFF + NH * 32 * 4)     // 57344

__global__ __launch_bounds__(384, 2) void finalize_kernel(
    const float* __restrict__ x, const float* __restrict__ lepe_w,
    const float* __restrict__ lepe_b, float* __restrict__ out)
{
    extern __shared__ __align__(16) uint8_t fsm[];
    __nv_bfloat16* Q = (__nv_bfloat16*)fsm;
    uint8_t* Bkv = fsm + FB_OFF;
    float* O  = (float*)fsm;                 // union: valid after MMA+sync
    float* zs = (float*)(fsm + FZ_OFF);

    int hh = blockIdx.x, half = blockIdx.y, b = blockIdx.z;
    int t = threadIdx.x;
    int h = t >> 5, lane = t & 31;
    bool even = ((lane & 1) == 0);
    int n0 = hh * HRES + half * 32;

    uint32_t qB = (uint32_t)__cvta_generic_to_shared(Q);

    {
        const __nv_bfloat16* qsrc = g_qrb + ((size_t)b * Ntok + n0) * Cch;
#pragma unroll
        for (int i = 0; i < 4; i++) {
            int idx = i * 384 + t;
            int row = idx / 48, col = idx % 48;
            cp16(qB + (uint32_t)(row * FQ_BYTES + col * 16),
                 qsrc + (size_t)row * Cch + col * 8);
        }
        asm volatile("cp.async.commit_group;");
    }

    float km  = g_ksum[b * Cch + t] * (1.0f / (float)Ntok);
    float kmp = __shfl_xor_sync(0xffffffffu, km, 1);

    {
        const float* kvh = g_kv + (size_t)(b * NH + h) * DH * DH;
        __nv_bfloat16* Bh = (__nv_bfloat16*)(Bkv + h * (DH * 80));
#pragma unroll
        for (int d = 0; d < DH; d++) {
            float v = kvh[d * DH + lane];
            Bh[lane * 40 + d] = __float2bfloat16(v);
        }
    }

    asm volatile("cp.async.wait_group 0;");
    __syncthreads();

#pragma unroll 4
    for (int w = 0; w < 32; w++) {
        float2 cs = g_rope[(size_t)(n0 + w) * 192 + (h * 16 + (lane >> 1))];
        float qv = __bfloat162float(Q[w * 392 + h * 32 + lane]);
        float rkm = even ? (cs.x * km - cs.y * kmp) : (cs.y * kmp + cs.x * km);
        float prod = qv * rkm;
#pragma unroll
        for (int o = 16; o > 0; o >>= 1)
            prod += __shfl_xor_sync(0xffffffffu, prod, o);
        if (lane == 0) zs[h * 32 + w] = 1.0f / (prod + 1e-6f);
    }
    __syncwarp();

    float4 c[2][4];
#pragma unroll
    for (int i = 0; i < 2; i++)
#pragma unroll
        for (int f = 0; f < 4; f++) c[i][f] = make_float4(0.f, 0.f, 0.f, 0.f);
    {
        int qq = lane >> 3, r8 = lane & 7;
        uint32_t aOff = (uint32_t)(((qq & 1) * 8 + r8) * FQ_BYTES + (qq >> 1) * 16);
        uint32_t bOff = (uint32_t)(((qq >> 1) * 8 + r8) * 80 + (qq & 1) * 16);
        uint32_t bB = (uint32_t)__cvta_generic_to_shared(Bkv) + (uint32_t)(h * DH * 80);
#pragma unroll
        for (int kk = 0; kk < 32; kk += 16) {
            uint32_t a[2][4], bb[2][4];
#pragma unroll
            for (int tf = 0; tf < 2; tf++)
                ldm_x4(a[tf], qB + (uint32_t)(tf * 16 * FQ_BYTES + (h * 32 + kk) * 2) + aOff);
#pragma unroll
            for (int bg = 0; bg < 2; bg++)
                ldm_x4(bb[bg], bB + (uint32_t)(bg * 16 * 80 + kk * 2) + bOff);
#pragma unroll
            for (int tf = 0; tf < 2; tf++)
#pragma unroll
                for (int bg = 0; bg < 2; bg++) {
                    mma16(c[tf][bg * 2],     a[tf], bb[bg][0], bb[bg][1]);
                    mma16(c[tf][bg * 2 + 1], a[tf], bb[bg][2], bb[bg][3]);
                }
        }
    }

    // Phase boundary: Q/Bkv dead, O takes over the same smem.
    __syncthreads();

    {
        int g = lane >> 2, l4 = lane & 3;
#pragma unroll
        for (int tf = 0; tf < 2; tf++) {
            float zlo = zs[h * 32 + tf * 16 + g];
            float zhi = zs[h * 32 + tf * 16 + g + 8];
#pragma unroll
            for (int f = 0; f < 4; f++) {
                int e = h * 32 + f * 8 + 2 * l4;
                float* lo = &O[(tf * 16 + g) * FO_STRIDE + e];
                float* hi = &O[(tf * 16 + g + 8) * FO_STRIDE + e];
                lo[0] = c[tf][f].x * zlo;  lo[1] = c[tf][f].y * zlo;
                hi[0] = c[tf][f].z * zhi;  hi[1] = c[tf][f].w * zhi;
            }
        }
    }
    __syncthreads();

    // Phase 4: chunked depthwise 3x3 conv (fp32 x) + add O
    float wl[9];
#pragma unroll
    for (int i = 0; i < 9; i++) wl[i] = lepe_w[t * 9 + i];
    float lb = lepe_b[t];

    const size_t rowStride = (size_t)HRES * Cch;
    const float* xb = x + (size_t)b * Ntok * Cch + t;
    int wb = half * 32;
    bool rok[3];
    const float* xr[3];
#pragma unroll
    for (int r = 0; r < 3; r++) {
        int yy = hh - 1 + r;
        rok[r] = (yy >= 0 && yy < HRES);
        xr[r] = xb + (size_t)(rok[r] ? yy : 0) * rowStride;
    }

    float* orow = out + ((size_t)b * Ntok + n0) * Cch + t;

#pragma unroll
    for (int ch = 0; ch < 4; ch++) {
        int base = wb + ch * 8;
        float v[3][10];
#pragma unroll
        for (int r = 0; r < 3; r++)
#pragma unroll
            for (int j = 0; j < 10; j++) {
                int col = base - 1 + j;
                bool ok = rok[r] && col >= 0 && col < HRES;
                v[r][j] = ok ? xr[r][(size_t)col * Cch] : 0.f;
            }
#pragma unroll
        for (int w = 0; w < 8; w++) {
            float lp = lb;
#pragma unroll
            for (int r = 0; r < 3; r++)
                lp += v[r][w] * wl[r * 3 + 0] + v[r][w + 1] * wl[r * 3 + 1]
                    + v[r][w + 2] * wl[r * 3 + 2];
            int wcol = ch * 8 + w;
            orow[(size_t)wcol * Cch] = lp + O[wcol * FO_STRIDE + t];
        }
    }
}

// ---------------------------------------------------------------------------
extern "C" void kernel_launch(void* const* d_in, const int* in_sizes, int n_in,
                              void* d_out, int out_size)
{
    const float* x      = (const float*)d_in[0];
    const float* qk_w   = (const float*)d_in[1];
    const float* qk_b   = (const float*)d_in[2];
    const float* lepe_w = (const float*)d_in[3];
    const float* lepe_b = (const float*)d_in[4];
    float* out = (float*)d_out;

    cudaFuncSetAttribute(gemm_rope_tc, cudaFuncAttributeMaxDynamicSharedMemorySize, GEMM_SMEM);
    cudaFuncSetAttribute(finalize_kernel, cudaFuncAttributeMaxDynamicSharedMemorySize, FIN_SMEM);

    setup_kernel<<<SB_W, 256>>>(x, qk_w);
    gemm_rope_tc<<<dim3(TWOC / BN, (Bsz * Ntok) / BM), 256, GEMM_SMEM>>>(qk_b);
    kv_kernel<<<dim3(Bsz, NH / 4, KVSPLIT), 256>>>();
    finalize_kernel<<<dim3(HRES, 2, Bsz), 384, FIN_SMEM>>>(x, lepe_w, lepe_b, out);
}

// round 11
// speedup vs baseline: 4.0642x; 1.0574x over previous
#include <cuda_runtime.h>
#include <cuda_bf16.h>
#include <cstdint>

#define Bsz 16
#define Ntok 4096
#define Cch 384
#define HRES 64
#define NH 12
#define DH 32
#define TWOC 768

// Scratch (device globals: allocation-free rule)
__device__ __nv_bfloat16 g_xbf[Bsz * Ntok * Cch];   // bf16 copy of x
__device__ __nv_bfloat16 g_wbf[TWOC * Cch];         // bf16 copy of qk_w
__device__ __nv_bfloat16 g_qrb[Bsz * Ntok * Cch];   // roped q (bf16)
__device__ __nv_bfloat16 g_krb[Bsz * Ntok * Cch];   // roped k (bf16)
__device__ float  g_ksum[Bsz * Cch];                // sum_n k (unroped, fp32)
__device__ float  g_kv  [Bsz * NH * DH * DH];
__device__ float2 g_rope[Ntok * (Cch / 2)];

// ---------------------------------------------------------------------------
__device__ __forceinline__ uint32_t packbf(float a, float b) {
    __nv_bfloat162 h = __float22bfloat162_rn(make_float2(a, b));
    return *reinterpret_cast<uint32_t*>(&h);
}

__device__ __forceinline__ void ldm_x4(uint32_t* d, uint32_t addr) {
    asm volatile("ldmatrix.sync.aligned.m8n8.x4.shared.b16 {%0,%1,%2,%3}, [%4];"
                 : "=r"(d[0]), "=r"(d[1]), "=r"(d[2]), "=r"(d[3]) : "r"(addr));
}

__device__ __forceinline__ void mma16(float4& d, const uint32_t* a,
                                      uint32_t b0, uint32_t b1) {
    asm volatile(
        "mma.sync.aligned.m16n8k16.row.col.f32.bf16.bf16.f32 "
        "{%0,%1,%2,%3},{%4,%5,%6,%7},{%8,%9},{%0,%1,%2,%3};\n"
        : "+f"(d.x), "+f"(d.y), "+f"(d.z), "+f"(d.w)
        : "r"(a[0]), "r"(a[1]), "r"(a[2]), "r"(a[3]), "r"(b0), "r"(b1));
}

__device__ __forceinline__ void cp16(uint32_t smem, const void* g) {
    asm volatile("cp.async.cg.shared.global [%0], [%1], 16;" :: "r"(smem), "l"(g));
}

// ---------------------------------------------------------------------------
// Fused setup: rope table + zero scratch + bf16 conversion, one launch.
// ---------------------------------------------------------------------------
#define SB_ROPE 3072
#define SB_ZERO (SB_ROPE + 768)
#define SB_X    (SB_ZERO + 12288)
#define SB_W    (SB_X + 144)

__global__ __launch_bounds__(256) void setup_kernel(
    const float* __restrict__ x, const float* __restrict__ w)
{
    int blk = blockIdx.x;
    if (blk < SB_ROPE) {
        int i = blk * 256 + threadIdx.x;      // < 786432
        int n = i / 192, p = i % 192;
        int hh = n >> 6, ww = n & 63;
        int j = (p < 96) ? p : (p - 96);
        float theta = __expf(-((float)j * (1.0f / 96.0f)) * 9.210340371976184f);
        float pos = (p < 96) ? (float)hh : (float)ww;
        float s, c;
        sincosf(pos * theta, &s, &c);
        g_rope[(size_t)n * 192 + p] = make_float2(c, s);
    } else if (blk < SB_ZERO) {
        int i = (blk - SB_ROPE) * 256 + threadIdx.x;   // < 196608
        if (i < Bsz * Cch) g_ksum[i] = 0.f;
        g_kv[i] = 0.f;
    } else if (blk < SB_X) {
        size_t o = ((size_t)(blk - SB_ZERO) * 256 + threadIdx.x) * 8;
        float4 a = *(const float4*)(x + o);
        float4 b = *(const float4*)(x + o + 4);
        uint4 u = make_uint4(packbf(a.x, a.y), packbf(a.z, a.w),
                             packbf(b.x, b.y), packbf(b.z, b.w));
        *(uint4*)&g_xbf[o] = u;
    } else {
        size_t o = ((size_t)(blk - SB_X) * 256 + threadIdx.x) * 8;
        if (o < (size_t)TWOC * Cch) {
            float4 a = *(const float4*)(w + o);
            float4 b = *(const float4*)(w + o + 4);
            uint4 u = make_uint4(packbf(a.x, a.y), packbf(a.z, a.w),
                                 packbf(b.x, b.y), packbf(b.z, b.w));
            *(uint4*)&g_wbf[o] = u;
        }
    }
}

// ---------------------------------------------------------------------------
// GEMM qk = x @ W^T + b via bf16 MMA, cp.async 3-stage pipeline.
// BM=128 BN=128 BK=32, 256 threads (8 warps: 2 in M x 4 in N), warp 64x32.
// ---------------------------------------------------------------------------
#define BM 128
#define BN 128
#define BK 32
#define STAGES 3
#define NKT (Cch / BK)          // 12
#define AROW 80                  // bytes per smem row (40 bf16)
#define ATILE (BM * AROW)        // 10240
#define WTILE (BN * AROW)        // 10240
#define GEMM_SMEM (STAGES * (ATILE + WTILE))   // 61440

__global__ __launch_bounds__(256, 2) void gemm_rope_tc(const float* __restrict__ bias)
{
    extern __shared__ __align__(16) uint8_t gsm[];
    uint8_t* smA = gsm;
    uint8_t* smW = gsm + STAGES * ATILE;

    int tid  = threadIdx.x;
    int warp = tid >> 5, lane = tid & 31;
    int wm = warp >> 2, wn = warp & 3;
    int g  = lane >> 2, l4 = lane & 3;
    int r8 = lane & 7,  qq = lane >> 3;

    int jBase = blockIdx.x * BN;
    int mBase = blockIdx.y * BM;

    const __nv_bfloat16* xblk = g_xbf + (size_t)mBase * Cch;
    const __nv_bfloat16* wblk = g_wbf + (size_t)jBase * Cch;

    int am[2], ak[2];
#pragma unroll
    for (int i = 0; i < 2; i++) { int idx = tid + i * 256; am[i] = idx >> 2; ak[i] = (idx & 3) * 8; }

    uint32_t aBase = (uint32_t)__cvta_generic_to_shared(smA);
    uint32_t wBase = (uint32_t)__cvta_generic_to_shared(smW);
    uint32_t aOff = (uint32_t)(((qq & 1) * 8 + r8) * AROW + (qq >> 1) * 16);
    uint32_t bOff = (uint32_t)(((qq >> 1) * 8 + r8) * AROW + (qq & 1) * 16);

    auto loadTile = [&](int t, int buf) {
        int k0 = t * BK;
#pragma unroll
        for (int i = 0; i < 2; i++) {
            cp16(aBase + (uint32_t)(buf * ATILE + am[i] * AROW + ak[i] * 2),
                 xblk + (size_t)am[i] * Cch + k0 + ak[i]);
            cp16(wBase + (uint32_t)(buf * WTILE + am[i] * AROW + ak[i] * 2),
                 wblk + (size_t)am[i] * Cch + k0 + ak[i]);
        }
        asm volatile("cp.async.commit_group;");
    };

    float4 c[4][4];
#pragma unroll
    for (int i = 0; i < 4; i++)
#pragma unroll
        for (int f = 0; f < 4; f++) c[i][f] = make_float4(0.f, 0.f, 0.f, 0.f);

    loadTile(0, 0);
    loadTile(1, 1);

    for (int t = 0; t < NKT; t++) {
        asm volatile("cp.async.wait_group 1;");
        __syncthreads();
        if (t + 2 < NKT) loadTile(t + 2, (t + 2) % STAGES);

        int buf = t % STAGES;
        uint32_t aT = aBase + (uint32_t)(buf * ATILE);
        uint32_t wT = wBase + (uint32_t)(buf * WTILE);
#pragma unroll
        for (int kk = 0; kk < BK; kk += 16) {
            uint32_t a[4][4], b[2][4];
#pragma unroll
            for (int mi = 0; mi < 4; mi++)
                ldm_x4(a[mi], aT + (uint32_t)((wm * 64 + mi * 16) * AROW + kk * 2) + aOff);
#pragma unroll
            for (int bg = 0; bg < 2; bg++)
                ldm_x4(b[bg], wT + (uint32_t)((wn * 32 + bg * 16) * AROW + kk * 2) + bOff);
#pragma unroll
            for (int mi = 0; mi < 4; mi++)
#pragma unroll
                for (int bg = 0; bg < 2; bg++) {
                    mma16(c[mi][bg * 2],     a[mi], b[bg][0], b[bg][1]);
                    mma16(c[mi][bg * 2 + 1], a[mi], b[bg][2], b[bg][3]);
                }
        }
    }

    // ---- fused epilogue: bias, elu+1, RoPE, k-sum; bf16 outputs ----
    bool isK = (jBase >= Cch);
    int bb = mBase >> 12;
    float ksum_loc[4][2];
#pragma unroll
    for (int f = 0; f < 4; f++) { ksum_loc[f][0] = 0.f; ksum_loc[f][1] = 0.f; }

#pragma unroll
    for (int mi = 0; mi < 4; mi++) {
        int mrow0 = mBase + wm * 64 + mi * 16 + g;
#pragma unroll
        for (int f = 0; f < 4; f++) {
            int j0 = jBase + wn * 32 + f * 8 + 2 * l4;
            int jm = isK ? (j0 - Cch) : j0;
            float b0 = bias[j0], b1 = bias[j0 + 1];
#pragma unroll
            for (int rr = 0; rr < 2; rr++) {
                int m = mrow0 + rr * 8;
                float re = (rr == 0 ? c[mi][f].x : c[mi][f].z) + b0;
                float im = (rr == 0 ? c[mi][f].y : c[mi][f].w) + b1;
                re = (re > 0.f) ? (re + 1.f) : __expf(re);
                im = (im > 0.f) ? (im + 1.f) : __expf(im);
                int n = m & (Ntok - 1);
                float2 cs = g_rope[(size_t)n * 192 + (jm >> 1)];
                float rre = cs.x * re - cs.y * im;
                float rim = cs.y * re + cs.x * im;
                size_t off = (size_t)m * Cch + jm;
                uint32_t pk = packbf(rre, rim);
                if (!isK) {
                    *(uint32_t*)&g_qrb[off] = pk;
                } else {
                    *(uint32_t*)&g_krb[off] = pk;
                    ksum_loc[f][0] += re;
                    ksum_loc[f][1] += im;
                }
            }
        }
    }

    if (isK) {
#pragma unroll
        for (int f = 0; f < 4; f++) {
#pragma unroll
            for (int e = 0; e < 2; e++) {
                float v = ksum_loc[f][e];
                v += __shfl_xor_sync(0xffffffffu, v, 4);
                v += __shfl_xor_sync(0xffffffffu, v, 8);
                v += __shfl_xor_sync(0xffffffffu, v, 16);
                if (g == 0) {
                    int jm = (jBase - Cch) + wn * 32 + f * 8 + 2 * l4 + e;
                    atomicAdd(&g_ksum[bb * Cch + jm], v);
                }
            }
        }
    }
}

// ---------------------------------------------------------------------------
// kv[b][h] += (1/N) sum_n outer(k_rope, v);  bf16 inputs, fp32 accumulate.
// ---------------------------------------------------------------------------
#define KVCH 32
#define KVSPLIT 32
#define KVROW 256
#define KVTILE (KVCH * KVROW)

__global__ __launch_bounds__(256) void kv_kernel()
{
    int b = blockIdx.x, hq = blockIdx.y, s = blockIdx.z;
    int tid = threadIdx.x;
    __shared__ __align__(16) uint8_t ksm[2 * KVTILE];
    __shared__ __align__(16) uint8_t vsm[2 * KVTILE];

    int sub = tid >> 6;
    int st  = tid & 63;
    int d0  = (st >> 3) * 4;
    int e0  = (st & 7) * 4;

    float a[4][4];
#pragma unroll
    for (int r = 0; r < 4; r++)
#pragma unroll
        for (int cc = 0; cc < 4; cc++) a[r][cc] = 0.f;

    const int CHUNK = Ntok / KVSPLIT;
    const int NSTG  = CHUNK / KVCH;
    int nBase = s * CHUNK;
    const __nv_bfloat16* kr = g_krb + ((size_t)b * Ntok + nBase) * Cch + hq * 128;
    const __nv_bfloat16* vv = g_xbf + ((size_t)b * Ntok + nBase) * Cch + hq * 128;

    int ln[2], lc[2];
#pragma unroll
    for (int i = 0; i < 2; i++) { int idx = tid + i * 256; ln[i] = idx >> 4; lc[i] = (idx & 15) * 8; }
    uint32_t ksB = (uint32_t)__cvta_generic_to_shared(ksm);
    uint32_t vsB = (uint32_t)__cvta_generic_to_shared(vsm);

    auto load_stage = [&](int stg, int buf) {
#pragma unroll
        for (int i = 0; i < 2; i++) {
            uint32_t so = (uint32_t)(buf * KVTILE + ln[i] * KVROW + lc[i] * 2);
            size_t go = (size_t)(stg * KVCH + ln[i]) * Cch + lc[i];
            cp16(ksB + so, kr + go);
            cp16(vsB + so, vv + go);
        }
        asm volatile("cp.async.commit_group;");
    };

    load_stage(0, 0);
    for (int stg = 0; stg < NSTG; stg++) {
        if (stg + 1 < NSTG) {
            load_stage(stg + 1, (stg + 1) & 1);
            asm volatile("cp.async.wait_group 1;");
        } else {
            asm volatile("cp.async.wait_group 0;");
        }
        __syncthreads();
        int buf = stg & 1;
        const uint8_t* kb = ksm + buf * KVTILE + (sub * 32 + d0) * 2;
        const uint8_t* vb = vsm + buf * KVTILE + (sub * 32 + e0) * 2;
#pragma unroll
        for (int n = 0; n < KVCH; n++) {
            const __nv_bfloat162* kp = (const __nv_bfloat162*)(kb + n * KVROW);
            const __nv_bfloat162* vp = (const __nv_bfloat162*)(vb + n * KVROW);
            float2 k01 = __bfloat1622float2(kp[0]);
            float2 k23 = __bfloat1622float2(kp[1]);
            float2 v01 = __bfloat1622float2(vp[0]);
            float2 v23 = __bfloat1622float2(vp[1]);
            float kk[4] = {k01.x, k01.y, k23.x, k23.y};
            float vr[4] = {v01.x, v01.y, v23.x, v23.y};
#pragma unroll
            for (int r = 0; r < 4; r++)
#pragma unroll
                for (int cc = 0; cc < 4; cc++) a[r][cc] += kk[r] * vr[cc];
        }
        __syncthreads();
    }

    const float inv = 1.0f / (float)Ntok;
    float* dst = g_kv + (size_t)(b * NH + hq * 4 + sub) * DH * DH;
#pragma unroll
    for (int r = 0; r < 4; r++)
#pragma unroll
        for (int cc = 0; cc < 4; cc++)
            atomicAdd(&dst[(d0 + r) * DH + e0 + cc], a[r][cc] * inv);
}

// ---------------------------------------------------------------------------
// Finalize: tensor-core attention epilogue + chunked depthwise conv (fp32 x).
// SMEM UNION (57KB) + __launch_bounds__(384,3): 3 blocks/SM (regs <= 56;
// smem 3x57344 = 172KB fits). Phase chain hidden by sibling blocks.
// ---------------------------------------------------------------------------
#define FQ_BYTES 784
#define FQ_SIZE  (32 * FQ_BYTES)            // 25088
#define FB_OFF   FQ_SIZE
#define FB_SIZE  (NH * DH * 80)             // 30720
#define FO_STRIDE 388
#define FO_SIZE  (32 * FO_STRIDE * 4)       // 49664  (< FQ_SIZE + FB_SIZE)
#define FZ_OFF   (FQ_SIZE + FB_SIZE)        // 55808
#define FIN_SMEM (FZ_OFF + NH * 32 * 4)     // 57344

__global__ __launch_bounds__(384, 3) void finalize_kernel(
    const float* __restrict__ x, const float* __restrict__ lepe_w,
    const float* __restrict__ lepe_b, float* __restrict__ out)
{
    extern __shared__ __align__(16) uint8_t fsm[];
    __nv_bfloat16* Q = (__nv_bfloat16*)fsm;
    uint8_t* Bkv = fsm + FB_OFF;
    float* O  = (float*)fsm;                 // union: valid after MMA+sync
    float* zs = (float*)(fsm + FZ_OFF);

    int hh = blockIdx.x, half = blockIdx.y, b = blockIdx.z;
    int t = threadIdx.x;
    int h = t >> 5, lane = t & 31;
    bool even = ((lane & 1) == 0);
    int n0 = hh * HRES + half * 32;

    uint32_t qB = (uint32_t)__cvta_generic_to_shared(Q);

    {
        const __nv_bfloat16* qsrc = g_qrb + ((size_t)b * Ntok + n0) * Cch;
#pragma unroll
        for (int i = 0; i < 4; i++) {
            int idx = i * 384 + t;
            int row = idx / 48, col = idx % 48;
            cp16(qB + (uint32_t)(row * FQ_BYTES + col * 16),
                 qsrc + (size_t)row * Cch + col * 8);
        }
        asm volatile("cp.async.commit_group;");
    }

    float km  = g_ksum[b * Cch + t] * (1.0f / (float)Ntok);
    float kmp = __shfl_xor_sync(0xffffffffu, km, 1);

    {
        const float* kvh = g_kv + (size_t)(b * NH + h) * DH * DH;
        __nv_bfloat16* Bh = (__nv_bfloat16*)(Bkv + h * (DH * 80));
#pragma unroll
        for (int d = 0; d < DH; d++) {
            float v = kvh[d * DH + lane];
            Bh[lane * 40 + d] = __float2bfloat16(v);
        }
    }

    asm volatile("cp.async.wait_group 0;");
    __syncthreads();

#pragma unroll 4
    for (int w = 0; w < 32; w++) {
        float2 cs = g_rope[(size_t)(n0 + w) * 192 + (h * 16 + (lane >> 1))];
        float qv = __bfloat162float(Q[w * 392 + h * 32 + lane]);
        float rkm = even ? (cs.x * km - cs.y * kmp) : (cs.y * kmp + cs.x * km);
        float prod = qv * rkm;
#pragma unroll
        for (int o = 16; o > 0; o >>= 1)
            prod += __shfl_xor_sync(0xffffffffu, prod, o);
        if (lane == 0) zs[h * 32 + w] = 1.0f / (prod + 1e-6f);
    }
    __syncwarp();

    float4 c[2][4];
#pragma unroll
    for (int i = 0; i < 2; i++)
#pragma unroll
        for (int f = 0; f < 4; f++) c[i][f] = make_float4(0.f, 0.f, 0.f, 0.f);
    {
        int qq = lane >> 3, r8 = lane & 7;
        uint32_t aOff = (uint32_t)(((qq & 1) * 8 + r8) * FQ_BYTES + (qq >> 1) * 16);
        uint32_t bOff = (uint32_t)(((qq >> 1) * 8 + r8) * 80 + (qq & 1) * 16);
        uint32_t bB = (uint32_t)__cvta_generic_to_shared(Bkv) + (uint32_t)(h * DH * 80);
#pragma unroll
        for (int kk = 0; kk < 32; kk += 16) {
            uint32_t a[2][4], bb[2][4];
#pragma unroll
            for (int tf = 0; tf < 2; tf++)
                ldm_x4(a[tf], qB + (uint32_t)(tf * 16 * FQ_BYTES + (h * 32 + kk) * 2) + aOff);
#pragma unroll
            for (int bg = 0; bg < 2; bg++)
                ldm_x4(bb[bg], bB + (uint32_t)(bg * 16 * 80 + kk * 2) + bOff);
#pragma unroll
            for (int tf = 0; tf < 2; tf++)
#pragma unroll
                for (int bg = 0; bg < 2; bg++) {
                    mma16(c[tf][bg * 2],     a[tf], bb[bg][0], bb[bg][1]);
                    mma16(c[tf][bg * 2 + 1], a[tf], bb[bg][2], bb[bg][3]);
                }
        }
    }

    // Phase boundary: Q/Bkv dead, O takes over the same smem.
    __syncthreads();

    {
        int g = lane >> 2, l4 = lane & 3;
#pragma unroll
        for (int tf = 0; tf < 2; tf++) {
            float zlo = zs[h * 32 + tf * 16 + g];
            float zhi = zs[h * 32 + tf * 16 + g + 8];
#pragma unroll
            for (int f = 0; f < 4; f++) {
                int e = h * 32 + f * 8 + 2 * l4;
                float* lo = &O[(tf * 16 + g) * FO_STRIDE + e];
                float* hi = &O[(tf * 16 + g + 8) * FO_STRIDE + e];
                lo[0] = c[tf][f].x * zlo;  lo[1] = c[tf][f].y * zlo;
                hi[0] = c[tf][f].z * zhi;  hi[1] = c[tf][f].w * zhi;
            }
        }
    }
    __syncthreads();

    // Phase 4: chunked depthwise 3x3 conv (fp32 x) + add O
    float wl[9];
#pragma unroll
    for (int i = 0; i < 9; i++) wl[i] = lepe_w[t * 9 + i];
    float lb = lepe_b[t];

    const size_t rowStride = (size_t)HRES * Cch;
    const float* xb = x + (size_t)b * Ntok * Cch + t;
    int wb = half * 32;
    bool rok[3];
    const float* xr[3];
#pragma unroll
    for (int r = 0; r < 3; r++) {
        int yy = hh - 1 + r;
        rok[r] = (yy >= 0 && yy < HRES);
        xr[r] = xb + (size_t)(rok[r] ? yy : 0) * rowStride;
    }

    float* orow = out + ((size_t)b * Ntok + n0) * Cch + t;

#pragma unroll
    for (int ch = 0; ch < 4; ch++) {
        int base = wb + ch * 8;
        float v[3][10];
#pragma unroll
        for (int r = 0; r < 3; r++)
#pragma unroll
            for (int j = 0; j < 10; j++) {
                int col = base - 1 + j;
                bool ok = rok[r] && col >= 0 && col < HRES;
                v[r][j] = ok ? xr[r][(size_t)col * Cch] : 0.f;
            }
#pragma unroll
        for (int w = 0; w < 8; w++) {
            float lp = lb;
#pragma unroll
            for (int r = 0; r < 3; r++)
                lp += v[r][w] * wl[r * 3 + 0] + v[r][w + 1] * wl[r * 3 + 1]
                    + v[r][w + 2] * wl[r * 3 + 2];
            int wcol = ch * 8 + w;
            orow[(size_t)wcol * Cch] = lp + O[wcol * FO_STRIDE + t];
        }
    }
}

// ---------------------------------------------------------------------------
extern "C" void kernel_launch(void* const* d_in, const int* in_sizes, int n_in,
                              void* d_out, int out_size)
{
    const float* x      = (const float*)d_in[0];
    const float* qk_w   = (const float*)d_in[1];
    const float* qk_b   = (const float*)d_in[2];
    const float* lepe_w = (const float*)d_in[3];
    const float* lepe_b = (const float*)d_in[4];
    float* out = (float*)d_out;

    cudaFuncSetAttribute(gemm_rope_tc, cudaFuncAttributeMaxDynamicSharedMemorySize, GEMM_SMEM);
    cudaFuncSetAttribute(finalize_kernel, cudaFuncAttributeMaxDynamicSharedMemorySize, FIN_SMEM);

    setup_kernel<<<SB_W, 256>>>(x, qk_w);
    gemm_rope_tc<<<dim3(TWOC / BN, (Bsz * Ntok) / BM), 256, GEMM_SMEM>>>(qk_b);
    kv_kernel<<<dim3(Bsz, NH / 4, KVSPLIT), 256>>>();
    finalize_kernel<<<dim3(HRES, 2, Bsz), 384, FIN_SMEM>>>(x, lepe_w, lepe_b, out);
}